// round 14
// baseline (speedup 1.0000x reference)
#include <cuda_runtime.h>
#include <cuda_fp16.h>
#include <math.h>

// Problem constants (fixed shapes)
#define NN 10000
#define EE 640000
#define FH 128          // F_IN == H == 128
#define CC 40
#define ZW 64           // z row width in halves (40 real + pad) = 128 B
#define BKT 256         // bucket capacity per node (max degree ~110 for this dist)
#define EO (EE / 8)     // edges handled 8-per-thread in build
#define GEMM_BLOCKS 157 // ceil(10000/64)
#define FUSE_BLOCKS 20  // 5120 outputs / 256
#define ZG_ROWS 64

typedef unsigned long long ull;

// ---------------- scratch (device globals; no allocation allowed) ----------------
// g_cnt is zero at process start (BSS) and re-zeroed at the end of k_agg2,
// so every kernel_launch execution sees zeroed counts (graph-replay safe).
// Row NN of g_h / g_ha / g_z is a permanent zero row (never written): gather pad.
__device__ __align__(256) int    g_cnt[NN];             // in-degree counts (no self-loop)
__device__ __align__(256) int    g_bkt[NN * BKT];       // padded adjacency buckets (src ids)
__device__ __align__(256) __half g_h[(NN + 1) * FH];    // GEMM1 output (fp16), scaled in place
__device__ __align__(256) __half g_ha[(NN + 1) * FH];   // layer-1 output (fp16, pre-scaled)
__device__ __align__(256) __half g_z[(NN + 1) * ZW];    // head-projected rows (fp16)
__device__ __align__(256) float  g_wf[FH * CC];         // Wfused = W2 @ Wc
__device__ __align__(256) float  g_bf[CC];              // bfused = b2 @ Wc + bc

// ---------------- packed f32x2 helpers (sm_103a) ----------------
__device__ __forceinline__ ull addf2(ull a, ull b) {
    ull r; asm("add.rn.f32x2 %0, %1, %2;" : "=l"(r) : "l"(a), "l"(b)); return r;
}
__device__ __forceinline__ ull h2tof2(unsigned int hv) {
    __half2 h = *reinterpret_cast<__half2*>(&hv);
    float2 f = __half22float2(h);
    ull r; asm("mov.b64 %0, {%1, %2};" : "=l"(r) : "f"(f.x), "f"(f.y)); return r;
}
__device__ __forceinline__ float2 unpackf2(ull a) {
    float2 f; asm("mov.b64 {%0, %1}, %2;" : "=f"(f.x), "=f"(f.y) : "l"(a)); return f;
}
__device__ __forceinline__ uint4 hadd2_v(uint4 a, uint4 b) {
    uint4 r;
    *(__half2*)&r.x = __hadd2(*(__half2*)&a.x, *(__half2*)&b.x);
    *(__half2*)&r.y = __hadd2(*(__half2*)&a.y, *(__half2*)&b.y);
    *(__half2*)&r.z = __hadd2(*(__half2*)&a.z, *(__half2*)&b.z);
    *(__half2*)&r.w = __hadd2(*(__half2*)&a.w, *(__half2*)&b.w);
    return r;
}
__device__ __forceinline__ int sel4(int4 v, int k) {
    return (k == 0) ? v.x : (k == 1) ? v.y : (k == 2) ? v.z : v.w;
}

// ---------------- kernel: bucket build (8 consecutive edges/thread, vector loads) ----------------
__global__ void k_build(const void* __restrict__ ei) {
    int t = blockIdx.x * blockDim.x + threadIdx.x;
    if (t >= EO) return;

    const int* __restrict__ w = (const int*)ei;
    bool is64 = true;
    #pragma unroll
    for (int j = 0; j < 8; j++)
        if (w[2 * j + 1] != 0) is64 = false;

    int s[8], d[8];
    if (!is64) {
        int4 sv0 = ((const int4*)w)[2 * t];
        int4 sv1 = ((const int4*)w)[2 * t + 1];
        int4 dv0 = ((const int4*)w)[EE / 4 + 2 * t];
        int4 dv1 = ((const int4*)w)[EE / 4 + 2 * t + 1];
        s[0] = sv0.x; s[1] = sv0.y; s[2] = sv0.z; s[3] = sv0.w;
        s[4] = sv1.x; s[5] = sv1.y; s[6] = sv1.z; s[7] = sv1.w;
        d[0] = dv0.x; d[1] = dv0.y; d[2] = dv0.z; d[3] = dv0.w;
        d[4] = dv1.x; d[5] = dv1.y; d[6] = dv1.z; d[7] = dv1.w;
    } else {
        const longlong2* __restrict__ L2s = (const longlong2*)ei;
        #pragma unroll
        for (int q = 0; q < 4; q++) {
            longlong2 a = L2s[4 * t + q];
            s[2 * q] = (int)a.x; s[2 * q + 1] = (int)a.y;
            longlong2 b = L2s[EE / 2 + 4 * t + q];
            d[2 * q] = (int)b.x; d[2 * q + 1] = (int)b.y;
        }
    }

    #pragma unroll
    for (int k = 0; k < 8; k++) {
        if ((unsigned)d[k] < NN && (unsigned)s[k] < NN) {
            int pos = atomicAdd(&g_cnt[d[k]], 1);
            if (pos < BKT - 4) g_bkt[d[k] * BKT + pos] = s[k];
        }
    }
}

// ---------------- GEMM (+ merged W2@Wc fold): C[M,128] = A[M,128] @ W[128,128], fp16 out ----------------
__global__ void k_gemm(const float* __restrict__ A, const float* __restrict__ W,
                       __half* __restrict__ Cmat,
                       const float* __restrict__ W2, const float* __restrict__ Wc,
                       const float* __restrict__ b2, const float* __restrict__ bc) {
    if (blockIdx.x >= GEMM_BLOCKS) {
        int idx = (blockIdx.x - GEMM_BLOCKS) * 256 + threadIdx.x;
        if (idx < FH * CC) {
            int k = idx / CC, c = idx % CC;
            float acc = 0.0f;
            #pragma unroll 8
            for (int j = 0; j < FH; j++)
                acc = fmaf(W2[k * FH + j], Wc[j * CC + c], acc);
            g_wf[idx] = acc;
        }
        if (idx < CC) {
            float acc = bc[idx];
            #pragma unroll 8
            for (int j = 0; j < FH; j++)
                acc = fmaf(b2[j], Wc[j * CC + idx], acc);
            g_bf[idx] = acc;
        }
        return;
    }

    __shared__ float As[64][32];
    __shared__ float Bs[32][128];
    int tid = threadIdx.x;
    int tx = tid & 15;
    int ty = tid >> 4;
    int rowBase = blockIdx.x * 64;

    float acc[4][8];
    #pragma unroll
    for (int j = 0; j < 4; j++)
        #pragma unroll
        for (int i = 0; i < 8; i++) acc[j][i] = 0.0f;

    for (int k0 = 0; k0 < 128; k0 += 32) {
        #pragma unroll
        for (int p = 0; p < 2; p++) {
            int f = tid + p * 256;
            int r = f >> 3, c4 = f & 7;
            int grow = rowBase + r;
            float4 v = make_float4(0.f, 0.f, 0.f, 0.f);
            if (grow < NN)
                v = *(const float4*)&A[grow * 128 + k0 + c4 * 4];
            *(float4*)&As[r][c4 * 4] = v;
        }
        #pragma unroll
        for (int p = 0; p < 4; p++) {
            int f = tid + p * 256;
            int r = f >> 5, c4 = f & 31;
            float4 v = *(const float4*)&W[(k0 + r) * 128 + c4 * 4];
            *(float4*)&Bs[r][c4 * 4] = v;
        }
        __syncthreads();
        #pragma unroll
        for (int kk = 0; kk < 32; kk++) {
            float a[4];
            #pragma unroll
            for (int j = 0; j < 4; j++) a[j] = As[ty * 4 + j][kk];
            float4 b0 = *(float4*)&Bs[kk][tx * 8];
            float4 b1 = *(float4*)&Bs[kk][tx * 8 + 4];
            float b[8] = {b0.x, b0.y, b0.z, b0.w, b1.x, b1.y, b1.z, b1.w};
            #pragma unroll
            for (int j = 0; j < 4; j++)
                #pragma unroll
                for (int i = 0; i < 8; i++)
                    acc[j][i] = fmaf(a[j], b[i], acc[j][i]);
        }
        __syncthreads();
    }

    #pragma unroll
    for (int j = 0; j < 4; j++) {
        int row = rowBase + ty * 4 + j;
        if (row < NN) {
            uint4 o;
            *(__half2*)&o.x = __floats2half2_rn(acc[j][0], acc[j][1]);
            *(__half2*)&o.y = __floats2half2_rn(acc[j][2], acc[j][3]);
            *(__half2*)&o.z = __floats2half2_rn(acc[j][4], acc[j][5]);
            *(__half2*)&o.w = __floats2half2_rn(acc[j][6], acc[j][7]);
            *(uint4*)&Cmat[row * 128 + tx * 8] = o;
        }
    }
}

// ---------------- kernel: in-place row scaling h' = dinv(row) * h + bucket self/pad ----------------
// Bucket list becomes [neighbors..., self, pads...] with length a multiple of 4.
__global__ void k_scale(__half* __restrict__ h) {
    int i = blockIdx.x * blockDim.x + threadIdx.x;
    if (i < NN) {
        int n = g_cnt[i]; if (n > BKT - 4) n = BKT - 4;
        int p = i * BKT;
        g_bkt[p + n] = i;                  // self entry
        int mlen = n + 1;
        #pragma unroll
        for (int q = 0; q < 3; q++) {
            if (mlen & 3) { g_bkt[p + mlen] = NN; mlen++; }
        }
    }
    if (i >= NN * FH / 8) return;
    int row = i >> 4;
    float d = rsqrtf((float)(g_cnt[row] + 1));
    uint4 v = ((uint4*)h)[i];
    __half2* p = (__half2*)&v;
    #pragma unroll
    for (int k = 0; k < 4; k++) {
        float2 f = __half22float2(p[k]);
        p[k] = __floats2half2_rn(f.x * d, f.y * d);
    }
    ((uint4*)h)[i] = v;
}

// ---------------- shared accumulate step: 8 rows -> HADD2 pair-reduce -> fp32 ----------------
__device__ __forceinline__ void acc8(ull& a0, ull& a1, ull& a2, ull& a3,
                                     uint4 v0, uint4 v1, uint4 v2, uint4 v3,
                                     uint4 v4, uint4 v5, uint4 v6, uint4 v7) {
    uint4 p0 = hadd2_v(v0, v1);
    uint4 p1 = hadd2_v(v2, v3);
    uint4 p2 = hadd2_v(v4, v5);
    uint4 p3 = hadd2_v(v6, v7);
    a0 = addf2(a0, h2tof2(p0.x)); a1 = addf2(a1, h2tof2(p0.y));
    a2 = addf2(a2, h2tof2(p0.z)); a3 = addf2(a3, h2tof2(p0.w));
    a0 = addf2(a0, h2tof2(p1.x)); a1 = addf2(a1, h2tof2(p1.y));
    a2 = addf2(a2, h2tof2(p1.z)); a3 = addf2(a3, h2tof2(p1.w));
    a0 = addf2(a0, h2tof2(p2.x)); a1 = addf2(a1, h2tof2(p2.y));
    a2 = addf2(a2, h2tof2(p2.z)); a3 = addf2(a3, h2tof2(p2.w));
    a0 = addf2(a0, h2tof2(p3.x)); a1 = addf2(a1, h2tof2(p3.y));
    a2 = addf2(a2, h2tof2(p3.z)); a3 = addf2(a3, h2tof2(p3.w));
}

// ---------------- gather: software-pipelined index prefetch (reg-heavy, measured best) ----------------
// lanes 0-15 even entries, lanes 16-31 odd; lane covers 8 halves of its row.
__device__ __forceinline__ void gather_pf(const __half* __restrict__ h,
                                          int node, int lane, int m,
                                          float out[8]) {
    int half = lane >> 4;
    int fl = lane & 15;
    const __half* __restrict__ rowoff = h + fl * 8;
    const int4* __restrict__ bp4 = (const int4*)&g_bkt[node * BKT];
    ull a0 = 0, a1 = 0, a2 = 0, a3 = 0;

    int e = 0;
    int4 nA, nB, nC, nD;
    if (e + 16 <= m) { nA = bp4[0]; nB = bp4[1]; nC = bp4[2]; nD = bp4[3]; }
    while (e + 16 <= m) {
        int4 iA = nA, iB = nB, iC = nC, iD = nD;
        int en = e + 16;
        if (en + 16 <= m) {
            nA = bp4[(en >> 2) + 0];
            nB = bp4[(en >> 2) + 1];
            nC = bp4[(en >> 2) + 2];
            nD = bp4[(en >> 2) + 3];
        }
        int s0 = half ? iA.y : iA.x;
        int s1 = half ? iA.w : iA.z;
        int s2 = half ? iB.y : iB.x;
        int s3 = half ? iB.w : iB.z;
        int s4 = half ? iC.y : iC.x;
        int s5 = half ? iC.w : iC.z;
        int s6 = half ? iD.y : iD.x;
        int s7 = half ? iD.w : iD.z;
        uint4 v0 = *(const uint4*)(rowoff + s0 * FH);
        uint4 v1 = *(const uint4*)(rowoff + s1 * FH);
        uint4 v2 = *(const uint4*)(rowoff + s2 * FH);
        uint4 v3 = *(const uint4*)(rowoff + s3 * FH);
        uint4 v4 = *(const uint4*)(rowoff + s4 * FH);
        uint4 v5 = *(const uint4*)(rowoff + s5 * FH);
        uint4 v6 = *(const uint4*)(rowoff + s6 * FH);
        uint4 v7 = *(const uint4*)(rowoff + s7 * FH);
        acc8(a0, a1, a2, a3, v0, v1, v2, v3, v4, v5, v6, v7);
        e = en;
    }
    const int* __restrict__ bp = (const int*)bp4;
    for (; e + 2 <= m; e += 2) {
        int s = bp[e + half];
        uint4 v = *(const uint4*)(rowoff + s * FH);
        a0 = addf2(a0, h2tof2(v.x)); a1 = addf2(a1, h2tof2(v.y));
        a2 = addf2(a2, h2tof2(v.z)); a3 = addf2(a3, h2tof2(v.w));
    }

    float2 f0 = unpackf2(a0), f1 = unpackf2(a1), f2 = unpackf2(a2), f3 = unpackf2(a3);
    out[0] = f0.x + __shfl_down_sync(0xFFFFFFFFu, f0.x, 16);
    out[1] = f0.y + __shfl_down_sync(0xFFFFFFFFu, f0.y, 16);
    out[2] = f1.x + __shfl_down_sync(0xFFFFFFFFu, f1.x, 16);
    out[3] = f1.y + __shfl_down_sync(0xFFFFFFFFu, f1.y, 16);
    out[4] = f2.x + __shfl_down_sync(0xFFFFFFFFu, f2.x, 16);
    out[5] = f2.y + __shfl_down_sync(0xFFFFFFFFu, f2.y, 16);
    out[6] = f3.x + __shfl_down_sync(0xFFFFFFFFu, f3.x, 16);
    out[7] = f3.y + __shfl_down_sync(0xFFFFFFFFu, f3.y, 16);
}

// ---------------- layer-1 agg: out' = dinv * relu(dinv*sum + b1)  (pre-scaled out) ----------------
// R11-measured config: 256 threads, prefetch gather, no occupancy cap.
__global__ void __launch_bounds__(256) k_agg1(const __half* __restrict__ h,
                                              const float* __restrict__ bias,
                                              __half* __restrict__ out) {
    int node = blockIdx.x * 8 + (threadIdx.x >> 5);
    if (node >= NN) return;
    int lane = threadIdx.x & 31;
    int n = g_cnt[node]; if (n > BKT - 4) n = BKT - 4;
    int m = (n + 4) & ~3;
    float di = rsqrtf((float)(n + 1));
    float f[8];
    gather_pf(h, node, lane, m, f);
    if (lane < 16) {
        float4 b0 = *(const float4*)&bias[lane * 8];
        float4 b1 = *(const float4*)&bias[lane * 8 + 4];
        float bb[8] = {b0.x, b0.y, b0.z, b0.w, b1.x, b1.y, b1.z, b1.w};
        float r[8];
        #pragma unroll
        for (int k = 0; k < 8; k++)
            r[k] = di * fmaxf(fmaf(f[k], di, bb[k]), 0.f);
        uint4 o;
        *(__half2*)&o.x = __floats2half2_rn(r[0], r[1]);
        *(__half2*)&o.y = __floats2half2_rn(r[2], r[3]);
        *(__half2*)&o.z = __floats2half2_rn(r[4], r[5]);
        *(__half2*)&o.w = __floats2half2_rn(r[6], r[7]);
        *(uint4*)&out[node * FH + lane * 8] = o;
    }
}

// ---------------- z-projection GEMM: z[NN x ZW fp16] = h1'[NN x 128] @ Wf[128 x 40] ----------------
// 64 rows/block, 256 threads; thread = 2 rows x 8 classes (register tiling).
__global__ void __launch_bounds__(256) k_zgemm(const __half* __restrict__ h1,
                                               __half* __restrict__ z) {
    __shared__ float Wfs[FH * ZW];           // 32 KB, classes zero-padded to 64
    __shared__ float As[ZG_ROWS][FH + 4];    // 33.8 KB, +4 pad for conflict-free reads

    int tid = threadIdx.x;
    int rowBase = blockIdx.x * ZG_ROWS;

    for (int i = tid; i < FH * ZW; i += 256) {
        int k = i >> 6, c = i & 63;
        Wfs[i] = (c < CC) ? g_wf[k * CC + c] : 0.0f;
    }
    for (int i = tid; i < ZG_ROWS * FH / 8; i += 256) {
        int r = i >> 4;
        int kc = (i & 15) * 8;
        int row = rowBase + r;
        uint4 v = make_uint4(0, 0, 0, 0);
        if (row < NN) v = *(const uint4*)&h1[row * FH + kc];
        __half2* p = (__half2*)&v;
        #pragma unroll
        for (int q = 0; q < 4; q++) {
            float2 f = __half22float2(p[q]);
            As[r][kc + 2 * q]     = f.x;
            As[r][kc + 2 * q + 1] = f.y;
        }
    }
    __syncthreads();

    int ty = tid >> 3;          // 0..31 -> rows 2ty, 2ty+1
    int tx = tid & 7;           // classes 8tx..8tx+8
    int r0 = 2 * ty, r1 = r0 + 1;
    int c0 = tx * 8;

    float acc0[8], acc1[8];
    #pragma unroll
    for (int j = 0; j < 8; j++) { acc0[j] = 0.f; acc1[j] = 0.f; }

    #pragma unroll 8
    for (int k = 0; k < FH; k++) {
        float a0 = As[r0][k];
        float a1 = As[r1][k];
        float4 b0 = *(float4*)&Wfs[k * ZW + c0];
        float4 b1 = *(float4*)&Wfs[k * ZW + c0 + 4];
        float b[8] = {b0.x, b0.y, b0.z, b0.w, b1.x, b1.y, b1.z, b1.w};
        #pragma unroll
        for (int j = 0; j < 8; j++) {
            acc0[j] = fmaf(a0, b[j], acc0[j]);
            acc1[j] = fmaf(a1, b[j], acc1[j]);
        }
    }

    int row0 = rowBase + r0;
    if (row0 < NN) {
        uint4 o;
        *(__half2*)&o.x = __floats2half2_rn(acc0[0], acc0[1]);
        *(__half2*)&o.y = __floats2half2_rn(acc0[2], acc0[3]);
        *(__half2*)&o.z = __floats2half2_rn(acc0[4], acc0[5]);
        *(__half2*)&o.w = __floats2half2_rn(acc0[6], acc0[7]);
        *(uint4*)&z[row0 * ZW + c0] = o;
    }
    int row1 = rowBase + r1;
    if (row1 < NN) {
        uint4 o;
        *(__half2*)&o.x = __floats2half2_rn(acc1[0], acc1[1]);
        *(__half2*)&o.y = __floats2half2_rn(acc1[2], acc1[3]);
        *(__half2*)&o.z = __floats2half2_rn(acc1[4], acc1[5]);
        *(__half2*)&o.w = __floats2half2_rn(acc1[6], acc1[7]);
        *(uint4*)&z[row1 * ZW + c0] = o;
    }
}

// ---------------- layer-2 agg over z rows (128 B each, 4 rows per LDG.128) + log-softmax ----------------
// 256 threads = 8 warps = 8 nodes per block.
__global__ void __launch_bounds__(256) k_agg2(const __half* __restrict__ z,
                                              float* __restrict__ out) {
    int tid = threadIdx.x;
    int lane = tid & 31;
    int node = blockIdx.x * 8 + (tid >> 5);
    if (node >= NN) return;

    int n = g_cnt[node]; if (n > BKT - 4) n = BKT - 4;
    int m = (n + 4) & ~3;
    float di = rsqrtf((float)(n + 1));

    int rsel = lane >> 3;          // which of 4 rows in a group
    int chunk = lane & 7;          // 8-half feature chunk
    const __half* __restrict__ zoff = z + chunk * 8;
    const int4* __restrict__ bp4 = (const int4*)&g_bkt[node * BKT];
    ull a0 = 0, a1 = 0, a2 = 0, a3 = 0;

    int e = 0;
    for (; e + 16 <= m; e += 16) {
        int4 iA = bp4[(e >> 2) + 0];
        int4 iB = bp4[(e >> 2) + 1];
        int4 iC = bp4[(e >> 2) + 2];
        int4 iD = bp4[(e >> 2) + 3];
        int s0 = sel4(iA, rsel);
        int s1 = sel4(iB, rsel);
        int s2 = sel4(iC, rsel);
        int s3 = sel4(iD, rsel);
        uint4 v0 = *(const uint4*)(zoff + s0 * ZW);
        uint4 v1 = *(const uint4*)(zoff + s1 * ZW);
        uint4 v2 = *(const uint4*)(zoff + s2 * ZW);
        uint4 v3 = *(const uint4*)(zoff + s3 * ZW);
        uint4 p0 = hadd2_v(v0, v1);
        uint4 p1 = hadd2_v(v2, v3);
        a0 = addf2(a0, h2tof2(p0.x)); a1 = addf2(a1, h2tof2(p0.y));
        a2 = addf2(a2, h2tof2(p0.z)); a3 = addf2(a3, h2tof2(p0.w));
        a0 = addf2(a0, h2tof2(p1.x)); a1 = addf2(a1, h2tof2(p1.y));
        a2 = addf2(a2, h2tof2(p1.z)); a3 = addf2(a3, h2tof2(p1.w));
    }
    const int* __restrict__ bp = (const int*)bp4;
    for (; e + 4 <= m; e += 4) {
        int s = bp[e + rsel];
        uint4 v = *(const uint4*)(zoff + s * ZW);
        a0 = addf2(a0, h2tof2(v.x)); a1 = addf2(a1, h2tof2(v.y));
        a2 = addf2(a2, h2tof2(v.z)); a3 = addf2(a3, h2tof2(v.w));
    }

    // combine row groups: lanes {l, l+8, l+16, l+24} hold same feature chunk
    float2 f0 = unpackf2(a0), f1 = unpackf2(a1), f2 = unpackf2(a2), f3 = unpackf2(a3);
    float v[8] = {f0.x, f0.y, f1.x, f1.y, f2.x, f2.y, f3.x, f3.y};
    #pragma unroll
    for (int j = 0; j < 8; j++) {
        v[j] += __shfl_down_sync(0xFFFFFFFFu, v[j], 16);
        v[j] += __shfl_down_sync(0xFFFFFFFFu, v[j], 8);
    }
    // lanes 0-7: chunk = lane, features base = lane*8
    int base = lane * 8;
    float lg[8];
    #pragma unroll
    for (int j = 0; j < 8; j++) {
        int c = base + j;
        lg[j] = (c < CC) ? fmaf(v[j], di, g_bf[c]) : -1e30f;
    }

    // reset count for the next graph replay (last reader of g_cnt)
    if (lane == 0) g_cnt[node] = 0;

    // log-softmax across lanes 0-7 (butterfly within group of 8)
    float mx = lg[0];
    #pragma unroll
    for (int j = 1; j < 8; j++) mx = fmaxf(mx, lg[j]);
    #pragma unroll
    for (int o = 4; o > 0; o >>= 1)
        mx = fmaxf(mx, __shfl_xor_sync(0xFFFFFFFFu, mx, o));
    float s = 0.0f;
    #pragma unroll
    for (int j = 0; j < 8; j++)
        if (base + j < CC) s += __expf(lg[j] - mx);
    #pragma unroll
    for (int o = 4; o > 0; o >>= 1)
        s += __shfl_xor_sync(0xFFFFFFFFu, s, o);
    float lse = mx + __logf(s);

    if (base < CC) {
        float4 o0 = make_float4(lg[0] - lse, lg[1] - lse, lg[2] - lse, lg[3] - lse);
        float4 o1 = make_float4(lg[4] - lse, lg[5] - lse, lg[6] - lse, lg[7] - lse);
        *(float4*)&out[node * CC + base]     = o0;
        *(float4*)&out[node * CC + base + 4] = o1;
    }
}

// ---------------- launch ----------------
extern "C" void kernel_launch(void* const* d_in, const int* in_sizes, int n_in,
                              void* d_out, int out_size) {
    const float* x   = (const float*)d_in[0];
    const void*  ei  = d_in[1];
    const float* W1  = (const float*)d_in[2];
    const float* b1  = (const float*)d_in[3];
    const float* W2  = (const float*)d_in[4];
    const float* b2  = (const float*)d_in[5];
    const float* Wc  = (const float*)d_in[6];
    const float* bc  = (const float*)d_in[7];
    float* out = (float*)d_out;

    __half* d_h;  cudaGetSymbolAddress((void**)&d_h,  g_h);
    __half* d_ha; cudaGetSymbolAddress((void**)&d_ha, g_ha);
    __half* d_z;  cudaGetSymbolAddress((void**)&d_z,  g_z);

    static cudaStream_t s2 = nullptr;
    static cudaEvent_t evFork = nullptr, evJoin = nullptr;
    if (!s2) {
        cudaStreamCreateWithFlags(&s2, cudaStreamNonBlocking);
        cudaEventCreateWithFlags(&evFork, cudaEventDisableTiming);
        cudaEventCreateWithFlags(&evJoin, cudaEventDisableTiming);
    }

    // fork: GEMM1 (x @ W1, + merged W2@Wc fold) is independent of edge structure
    cudaEventRecord(evFork, 0);
    cudaStreamWaitEvent(s2, evFork, 0);
    k_gemm<<<GEMM_BLOCKS + FUSE_BLOCKS, 256, 0, s2>>>(x, W1, d_h, W2, Wc, b2, bc);
    cudaEventRecord(evJoin, s2);

    // bucket build on main stream (concurrent with s2); counts arrive zeroed
    k_build<<<(EO + 255) / 256, 256>>>(ei);

    // join: scale needs both counts (build) and h (gemm1)
    cudaStreamWaitEvent(0, evJoin, 0);
    k_scale<<<(NN * FH / 8 + 255) / 256, 256>>>(d_h);

    // layer 1 aggregate (pre-scaled h1' rows)
    k_agg1<<<(NN + 7) / 8, 256>>>(d_h, b1, d_ha);
    // head projection GEMM: z = h1' @ Wf
    k_zgemm<<<GEMM_BLOCKS, 256>>>(d_ha, d_z);
    // layer 2 aggregate over z + log-softmax (also re-zeroes counts)
    k_agg2<<<(NN + 7) / 8, 256>>>(d_z, out);
}

// round 15
// speedup vs baseline: 1.0430x; 1.0430x over previous
#include <cuda_runtime.h>
#include <cuda_fp16.h>
#include <math.h>

// Problem constants (fixed shapes)
#define NN 10000
#define EE 640000
#define FH 128          // F_IN == H == 128
#define CC 40
#define ZW 64           // z row width in halves (40 real + pad) = 128 B
#define BKT 256         // bucket capacity per node (max degree ~110 for this dist)
#define EO (EE / 8)     // edges handled 8-per-thread in build
#define GEMM_BLOCKS 313 // ceil(10000/32)
#define FUSE_BLOCKS 20  // 5120 outputs / 256

typedef unsigned long long ull;

// ---------------- scratch (device globals; no allocation allowed) ----------------
// g_cnt is zero at process start (BSS) and re-zeroed at the end of k_agg2,
// so every kernel_launch execution sees zeroed counts (graph-replay safe).
// Row NN of g_h / g_z is a permanent zero row (never written): gather pad.
__device__ __align__(256) int    g_cnt[NN];             // in-degree counts (no self-loop)
__device__ __align__(256) int    g_bkt[NN * BKT];       // padded adjacency buckets (src ids)
__device__ __align__(256) __half g_h[(NN + 1) * FH];    // GEMM1 output (fp16), scaled in place
__device__ __align__(256) __half g_z[(NN + 1) * ZW];    // head-projected rows (fp16)
__device__ __align__(256) float  g_wf[FH * CC];         // Wfused = W2 @ Wc
__device__ __align__(256) float  g_bf[CC];              // bfused = b2 @ Wc + bc

// ---------------- packed f32x2 helpers (sm_103a) ----------------
__device__ __forceinline__ ull addf2(ull a, ull b) {
    ull r; asm("add.rn.f32x2 %0, %1, %2;" : "=l"(r) : "l"(a), "l"(b)); return r;
}
__device__ __forceinline__ ull h2tof2(unsigned int hv) {
    __half2 h = *reinterpret_cast<__half2*>(&hv);
    float2 f = __half22float2(h);
    ull r; asm("mov.b64 %0, {%1, %2};" : "=l"(r) : "f"(f.x), "f"(f.y)); return r;
}
__device__ __forceinline__ float2 unpackf2(ull a) {
    float2 f; asm("mov.b64 {%0, %1}, %2;" : "=f"(f.x), "=f"(f.y) : "l"(a)); return f;
}
__device__ __forceinline__ uint4 hadd2_v(uint4 a, uint4 b) {
    uint4 r;
    *(__half2*)&r.x = __hadd2(*(__half2*)&a.x, *(__half2*)&b.x);
    *(__half2*)&r.y = __hadd2(*(__half2*)&a.y, *(__half2*)&b.y);
    *(__half2*)&r.z = __hadd2(*(__half2*)&a.z, *(__half2*)&b.z);
    *(__half2*)&r.w = __hadd2(*(__half2*)&a.w, *(__half2*)&b.w);
    return r;
}
__device__ __forceinline__ int sel4(int4 v, int k) {
    return (k == 0) ? v.x : (k == 1) ? v.y : (k == 2) ? v.z : v.w;
}

// ---------------- kernel: bucket build (8 consecutive edges/thread, vector loads) ----------------
__global__ void k_build(const void* __restrict__ ei) {
    int t = blockIdx.x * blockDim.x + threadIdx.x;
    if (t >= EO) return;

    const int* __restrict__ w = (const int*)ei;
    bool is64 = true;
    #pragma unroll
    for (int j = 0; j < 8; j++)
        if (w[2 * j + 1] != 0) is64 = false;

    int s[8], d[8];
    if (!is64) {
        int4 sv0 = ((const int4*)w)[2 * t];
        int4 sv1 = ((const int4*)w)[2 * t + 1];
        int4 dv0 = ((const int4*)w)[EE / 4 + 2 * t];
        int4 dv1 = ((const int4*)w)[EE / 4 + 2 * t + 1];
        s[0] = sv0.x; s[1] = sv0.y; s[2] = sv0.z; s[3] = sv0.w;
        s[4] = sv1.x; s[5] = sv1.y; s[6] = sv1.z; s[7] = sv1.w;
        d[0] = dv0.x; d[1] = dv0.y; d[2] = dv0.z; d[3] = dv0.w;
        d[4] = dv1.x; d[5] = dv1.y; d[6] = dv1.z; d[7] = dv1.w;
    } else {
        const longlong2* __restrict__ L2s = (const longlong2*)ei;
        #pragma unroll
        for (int q = 0; q < 4; q++) {
            longlong2 a = L2s[4 * t + q];
            s[2 * q] = (int)a.x; s[2 * q + 1] = (int)a.y;
            longlong2 b = L2s[EE / 2 + 4 * t + q];
            d[2 * q] = (int)b.x; d[2 * q + 1] = (int)b.y;
        }
    }

    #pragma unroll
    for (int k = 0; k < 8; k++) {
        if ((unsigned)d[k] < NN && (unsigned)s[k] < NN) {
            int pos = atomicAdd(&g_cnt[d[k]], 1);
            if (pos < BKT - 4) g_bkt[d[k] * BKT + pos] = s[k];
        }
    }
}

// ---------------- GEMM (+ merged W2@Wc fold): C[M,128] = A[M,128] @ W[128,128], fp16 out ----------------
// BM=32 (313 blocks -> ~2 blocks/SM for latency hiding), 256 threads, 2x8 per thread.
__global__ void k_gemm(const float* __restrict__ A, const float* __restrict__ W,
                       __half* __restrict__ Cmat,
                       const float* __restrict__ W2, const float* __restrict__ Wc,
                       const float* __restrict__ b2, const float* __restrict__ bc) {
    if (blockIdx.x >= GEMM_BLOCKS) {
        int idx = (blockIdx.x - GEMM_BLOCKS) * 256 + threadIdx.x;
        if (idx < FH * CC) {
            int k = idx / CC, c = idx % CC;
            float acc = 0.0f;
            #pragma unroll 8
            for (int j = 0; j < FH; j++)
                acc = fmaf(W2[k * FH + j], Wc[j * CC + c], acc);
            g_wf[idx] = acc;
        }
        if (idx < CC) {
            float acc = bc[idx];
            #pragma unroll 8
            for (int j = 0; j < FH; j++)
                acc = fmaf(b2[j], Wc[j * CC + idx], acc);
            g_bf[idx] = acc;
        }
        return;
    }

    __shared__ float As[32][32];
    __shared__ float Bs[32][128];
    int tid = threadIdx.x;
    int tx = tid & 15;          // 8 cols each
    int ty = tid >> 4;          // 0..15 -> 2 rows each
    int rowBase = blockIdx.x * 32;

    float acc[2][8];
    #pragma unroll
    for (int j = 0; j < 2; j++)
        #pragma unroll
        for (int i = 0; i < 8; i++) acc[j][i] = 0.0f;

    for (int k0 = 0; k0 < 128; k0 += 32) {
        // A tile: 32x32 = 256 float4, 1 per thread
        {
            int r = tid >> 3, c4 = tid & 7;
            int grow = rowBase + r;
            float4 v = make_float4(0.f, 0.f, 0.f, 0.f);
            if (grow < NN)
                v = *(const float4*)&A[grow * 128 + k0 + c4 * 4];
            *(float4*)&As[r][c4 * 4] = v;
        }
        // B tile: 32x128 = 1024 float4, 4 per thread
        #pragma unroll
        for (int p = 0; p < 4; p++) {
            int f = tid + p * 256;
            int r = f >> 5, c4 = f & 31;
            float4 v = *(const float4*)&W[(k0 + r) * 128 + c4 * 4];
            *(float4*)&Bs[r][c4 * 4] = v;
        }
        __syncthreads();
        #pragma unroll
        for (int kk = 0; kk < 32; kk++) {
            float a0 = As[ty * 2][kk];
            float a1 = As[ty * 2 + 1][kk];
            float4 b0 = *(float4*)&Bs[kk][tx * 8];
            float4 b1 = *(float4*)&Bs[kk][tx * 8 + 4];
            float b[8] = {b0.x, b0.y, b0.z, b0.w, b1.x, b1.y, b1.z, b1.w};
            #pragma unroll
            for (int i = 0; i < 8; i++) {
                acc[0][i] = fmaf(a0, b[i], acc[0][i]);
                acc[1][i] = fmaf(a1, b[i], acc[1][i]);
            }
        }
        __syncthreads();
    }

    #pragma unroll
    for (int j = 0; j < 2; j++) {
        int row = rowBase + ty * 2 + j;
        if (row < NN) {
            uint4 o;
            *(__half2*)&o.x = __floats2half2_rn(acc[j][0], acc[j][1]);
            *(__half2*)&o.y = __floats2half2_rn(acc[j][2], acc[j][3]);
            *(__half2*)&o.z = __floats2half2_rn(acc[j][4], acc[j][5]);
            *(__half2*)&o.w = __floats2half2_rn(acc[j][6], acc[j][7]);
            *(uint4*)&Cmat[row * 128 + tx * 8] = o;
        }
    }
}

// ---------------- kernel: in-place row scaling h' = dinv(row) * h + bucket self/pad ----------------
// Bucket list becomes [neighbors..., self, pads...] with length a multiple of 4.
__global__ void k_scale(__half* __restrict__ h) {
    int i = blockIdx.x * blockDim.x + threadIdx.x;
    if (i < NN) {
        int n = g_cnt[i]; if (n > BKT - 4) n = BKT - 4;
        int p = i * BKT;
        g_bkt[p + n] = i;                  // self entry
        int mlen = n + 1;
        #pragma unroll
        for (int q = 0; q < 3; q++) {
            if (mlen & 3) { g_bkt[p + mlen] = NN; mlen++; }
        }
    }
    if (i >= NN * FH / 8) return;
    int row = i >> 4;
    float d = rsqrtf((float)(g_cnt[row] + 1));
    uint4 v = ((uint4*)h)[i];
    __half2* p = (__half2*)&v;
    #pragma unroll
    for (int k = 0; k < 4; k++) {
        float2 f = __half22float2(p[k]);
        p[k] = __floats2half2_rn(f.x * d, f.y * d);
    }
    ((uint4*)h)[i] = v;
}

// ---------------- shared accumulate step: 8 rows -> HADD2 pair-reduce -> fp32 ----------------
__device__ __forceinline__ void acc8(ull& a0, ull& a1, ull& a2, ull& a3,
                                     uint4 v0, uint4 v1, uint4 v2, uint4 v3,
                                     uint4 v4, uint4 v5, uint4 v6, uint4 v7) {
    uint4 p0 = hadd2_v(v0, v1);
    uint4 p1 = hadd2_v(v2, v3);
    uint4 p2 = hadd2_v(v4, v5);
    uint4 p3 = hadd2_v(v6, v7);
    a0 = addf2(a0, h2tof2(p0.x)); a1 = addf2(a1, h2tof2(p0.y));
    a2 = addf2(a2, h2tof2(p0.z)); a3 = addf2(a3, h2tof2(p0.w));
    a0 = addf2(a0, h2tof2(p1.x)); a1 = addf2(a1, h2tof2(p1.y));
    a2 = addf2(a2, h2tof2(p1.z)); a3 = addf2(a3, h2tof2(p1.w));
    a0 = addf2(a0, h2tof2(p2.x)); a1 = addf2(a1, h2tof2(p2.y));
    a2 = addf2(a2, h2tof2(p2.z)); a3 = addf2(a3, h2tof2(p2.w));
    a0 = addf2(a0, h2tof2(p3.x)); a1 = addf2(a1, h2tof2(p3.y));
    a2 = addf2(a2, h2tof2(p3.z)); a3 = addf2(a3, h2tof2(p3.w));
}

// ---------------- gather: plain, reg-lean (2 rows per LDG.128, HADD2 pre-reduce) ----------------
__device__ __forceinline__ void gather_plain(const __half* __restrict__ h,
                                             int node, int lane, int m,
                                             float out[8]) {
    int half = lane >> 4;
    int fl = lane & 15;
    const __half* __restrict__ rowoff = h + fl * 8;
    const int4* __restrict__ bp4 = (const int4*)&g_bkt[node * BKT];
    ull a0 = 0, a1 = 0, a2 = 0, a3 = 0;

    int e = 0;
    for (; e + 16 <= m; e += 16) {
        int4 iA = bp4[(e >> 2) + 0];
        int4 iB = bp4[(e >> 2) + 1];
        int4 iC = bp4[(e >> 2) + 2];
        int4 iD = bp4[(e >> 2) + 3];
        int s0 = half ? iA.y : iA.x;
        int s1 = half ? iA.w : iA.z;
        int s2 = half ? iB.y : iB.x;
        int s3 = half ? iB.w : iB.z;
        int s4 = half ? iC.y : iC.x;
        int s5 = half ? iC.w : iC.z;
        int s6 = half ? iD.y : iD.x;
        int s7 = half ? iD.w : iD.z;
        uint4 v0 = *(const uint4*)(rowoff + s0 * FH);
        uint4 v1 = *(const uint4*)(rowoff + s1 * FH);
        uint4 v2 = *(const uint4*)(rowoff + s2 * FH);
        uint4 v3 = *(const uint4*)(rowoff + s3 * FH);
        uint4 v4 = *(const uint4*)(rowoff + s4 * FH);
        uint4 v5 = *(const uint4*)(rowoff + s5 * FH);
        uint4 v6 = *(const uint4*)(rowoff + s6 * FH);
        uint4 v7 = *(const uint4*)(rowoff + s7 * FH);
        acc8(a0, a1, a2, a3, v0, v1, v2, v3, v4, v5, v6, v7);
    }
    const int* __restrict__ bp = (const int*)bp4;
    for (; e + 2 <= m; e += 2) {
        int s = bp[e + half];
        uint4 v = *(const uint4*)(rowoff + s * FH);
        a0 = addf2(a0, h2tof2(v.x)); a1 = addf2(a1, h2tof2(v.y));
        a2 = addf2(a2, h2tof2(v.z)); a3 = addf2(a3, h2tof2(v.w));
    }

    float2 f0 = unpackf2(a0), f1 = unpackf2(a1), f2 = unpackf2(a2), f3 = unpackf2(a3);
    out[0] = f0.x + __shfl_down_sync(0xFFFFFFFFu, f0.x, 16);
    out[1] = f0.y + __shfl_down_sync(0xFFFFFFFFu, f0.y, 16);
    out[2] = f1.x + __shfl_down_sync(0xFFFFFFFFu, f1.x, 16);
    out[3] = f1.y + __shfl_down_sync(0xFFFFFFFFu, f1.y, 16);
    out[4] = f2.x + __shfl_down_sync(0xFFFFFFFFu, f2.x, 16);
    out[5] = f2.y + __shfl_down_sync(0xFFFFFFFFu, f2.y, 16);
    out[6] = f3.x + __shfl_down_sync(0xFFFFFFFFu, f3.x, 16);
    out[7] = f3.y + __shfl_down_sync(0xFFFFFFFFu, f3.y, 16);
}

// ---------------- layer-1 agg + head projection (float2-paired matvec) ----------------
// 512 threads = 16 warps = 16 nodes per block; capped at 3 blocks/SM.
// z[node] = (dinv * relu(dinv*sum + b1)) @ Wf, stored as 64 fp16 (40 real + zero pad).
__global__ void __launch_bounds__(512, 3) k_agg1_proj(const __half* __restrict__ h,
                                                      const float* __restrict__ bias,
                                                      __half* __restrict__ z) {
    __shared__ float2 Wf2s[64 * CC];     // k-paired Wf: 20.5 KB
    __shared__ float2 hrow2[16 * 64];    // k-paired h1 rows: 8 KB

    int tid = threadIdx.x;
    int lane = tid & 31;
    int w = tid >> 5;
    for (int i = tid; i < 64 * CC; i += 512) {
        int k2 = i / CC, c = i - k2 * CC;
        Wf2s[i] = make_float2(g_wf[(2 * k2) * CC + c], g_wf[(2 * k2 + 1) * CC + c]);
    }
    __syncthreads();

    int node = blockIdx.x * 16 + w;
    if (node >= NN) return;

    int n = g_cnt[node]; if (n > BKT - 4) n = BKT - 4;
    int m = (n + 4) & ~3;
    float di = rsqrtf((float)(n + 1));
    float f[8];
    gather_plain(h, node, lane, m, f);
    if (lane < 16) {
        float4 b0 = *(const float4*)&bias[lane * 8];
        float4 b1 = *(const float4*)&bias[lane * 8 + 4];
        float bb[8] = {b0.x, b0.y, b0.z, b0.w, b1.x, b1.y, b1.z, b1.w};
        float r[8];
        #pragma unroll
        for (int k = 0; k < 8; k++)
            r[k] = di * fmaxf(fmaf(f[k], di, bb[k]), 0.f);
        // lane covers k = 8*lane..8*lane+7 -> float2 pairs k2 = 4*lane..4*lane+3
        float4 o0 = make_float4(r[0], r[1], r[2], r[3]);
        float4 o1 = make_float4(r[4], r[5], r[6], r[7]);
        *(float4*)&hrow2[w * 64 + 4 * lane]     = o0;   // 2 float2s
        *(float4*)&hrow2[w * 64 + 4 * lane + 2] = o1;   // 2 float2s
    }
    __syncwarp();

    // head projection: z_c = sum_k2 hrow2[k2] . Wf2[k2][c]; lane handles c0=lane, c1=lane+32
    int c0 = lane;
    int c1 = lane + 32;
    float z0 = 0.0f, z1 = 0.0f;
    const float2* __restrict__ hp = &hrow2[w * 64];
    #pragma unroll 4
    for (int k2 = 0; k2 < 64; k2++) {
        float2 hv = hp[k2];
        float2 wa = Wf2s[k2 * CC + c0];
        z0 = fmaf(hv.x, wa.x, z0);
        z0 = fmaf(hv.y, wa.y, z0);
        if (c1 < CC) {
            float2 wb = Wf2s[k2 * CC + c1];
            z1 = fmaf(hv.x, wb.x, z1);
            z1 = fmaf(hv.y, wb.y, z1);
        }
    }
    // z row = 64 halves: [0..39] real, [40..63] zero
    z[node * ZW + lane] = __float2half(z0);
    z[node * ZW + 32 + lane] = (c1 < CC) ? __float2half(z1) : __half(0.0f);
}

// ---------------- layer-2 agg over z rows (128 B each, 4 rows per LDG.128) + log-softmax ----------------
// 256 threads = 8 warps = 8 nodes per block.
__global__ void __launch_bounds__(256) k_agg2(const __half* __restrict__ z,
                                              float* __restrict__ out) {
    int tid = threadIdx.x;
    int lane = tid & 31;
    int node = blockIdx.x * 8 + (tid >> 5);
    if (node >= NN) return;

    int n = g_cnt[node]; if (n > BKT - 4) n = BKT - 4;
    int m = (n + 4) & ~3;
    float di = rsqrtf((float)(n + 1));

    int rsel = lane >> 3;          // which of 4 rows in a group
    int chunk = lane & 7;          // 8-half feature chunk
    const __half* __restrict__ zoff = z + chunk * 8;
    const int4* __restrict__ bp4 = (const int4*)&g_bkt[node * BKT];
    ull a0 = 0, a1 = 0, a2 = 0, a3 = 0;

    int e = 0;
    for (; e + 16 <= m; e += 16) {
        int4 iA = bp4[(e >> 2) + 0];
        int4 iB = bp4[(e >> 2) + 1];
        int4 iC = bp4[(e >> 2) + 2];
        int4 iD = bp4[(e >> 2) + 3];
        int s0 = sel4(iA, rsel);
        int s1 = sel4(iB, rsel);
        int s2 = sel4(iC, rsel);
        int s3 = sel4(iD, rsel);
        uint4 v0 = *(const uint4*)(zoff + s0 * ZW);
        uint4 v1 = *(const uint4*)(zoff + s1 * ZW);
        uint4 v2 = *(const uint4*)(zoff + s2 * ZW);
        uint4 v3 = *(const uint4*)(zoff + s3 * ZW);
        uint4 p0 = hadd2_v(v0, v1);
        uint4 p1 = hadd2_v(v2, v3);
        a0 = addf2(a0, h2tof2(p0.x)); a1 = addf2(a1, h2tof2(p0.y));
        a2 = addf2(a2, h2tof2(p0.z)); a3 = addf2(a3, h2tof2(p0.w));
        a0 = addf2(a0, h2tof2(p1.x)); a1 = addf2(a1, h2tof2(p1.y));
        a2 = addf2(a2, h2tof2(p1.z)); a3 = addf2(a3, h2tof2(p1.w));
    }
    const int* __restrict__ bp = (const int*)bp4;
    for (; e + 4 <= m; e += 4) {
        int s = bp[e + rsel];
        uint4 v = *(const uint4*)(zoff + s * ZW);
        a0 = addf2(a0, h2tof2(v.x)); a1 = addf2(a1, h2tof2(v.y));
        a2 = addf2(a2, h2tof2(v.z)); a3 = addf2(a3, h2tof2(v.w));
    }

    // combine row groups: lanes {l, l+8, l+16, l+24} hold same feature chunk
    float2 f0 = unpackf2(a0), f1 = unpackf2(a1), f2 = unpackf2(a2), f3 = unpackf2(a3);
    float v[8] = {f0.x, f0.y, f1.x, f1.y, f2.x, f2.y, f3.x, f3.y};
    #pragma unroll
    for (int j = 0; j < 8; j++) {
        v[j] += __shfl_down_sync(0xFFFFFFFFu, v[j], 16);
        v[j] += __shfl_down_sync(0xFFFFFFFFu, v[j], 8);
    }
    // lanes 0-7: chunk = lane, features base = lane*8
    int base = lane * 8;
    float lg[8];
    #pragma unroll
    for (int j = 0; j < 8; j++) {
        int c = base + j;
        lg[j] = (c < CC) ? fmaf(v[j], di, g_bf[c]) : -1e30f;
    }

    // reset count for the next graph replay (last reader of g_cnt)
    if (lane == 0) g_cnt[node] = 0;

    // log-softmax across lanes 0-7 (butterfly within group of 8)
    float mx = lg[0];
    #pragma unroll
    for (int j = 1; j < 8; j++) mx = fmaxf(mx, lg[j]);
    #pragma unroll
    for (int o = 4; o > 0; o >>= 1)
        mx = fmaxf(mx, __shfl_xor_sync(0xFFFFFFFFu, mx, o));
    float s = 0.0f;
    #pragma unroll
    for (int j = 0; j < 8; j++)
        if (base + j < CC) s += __expf(lg[j] - mx);
    #pragma unroll
    for (int o = 4; o > 0; o >>= 1)
        s += __shfl_xor_sync(0xFFFFFFFFu, s, o);
    float lse = mx + __logf(s);

    if (base < CC) {
        float4 o0 = make_float4(lg[0] - lse, lg[1] - lse, lg[2] - lse, lg[3] - lse);
        float4 o1 = make_float4(lg[4] - lse, lg[5] - lse, lg[6] - lse, lg[7] - lse);
        *(float4*)&out[node * CC + base]     = o0;
        *(float4*)&out[node * CC + base + 4] = o1;
    }
}

// ---------------- launch ----------------
extern "C" void kernel_launch(void* const* d_in, const int* in_sizes, int n_in,
                              void* d_out, int out_size) {
    const float* x   = (const float*)d_in[0];
    const void*  ei  = d_in[1];
    const float* W1  = (const float*)d_in[2];
    const float* b1  = (const float*)d_in[3];
    const float* W2  = (const float*)d_in[4];
    const float* b2  = (const float*)d_in[5];
    const float* Wc  = (const float*)d_in[6];
    const float* bc  = (const float*)d_in[7];
    float* out = (float*)d_out;

    __half* d_h; cudaGetSymbolAddress((void**)&d_h, g_h);
    __half* d_z; cudaGetSymbolAddress((void**)&d_z, g_z);

    static cudaStream_t s2 = nullptr;
    static cudaEvent_t evFork = nullptr, evJoin = nullptr;
    if (!s2) {
        cudaStreamCreateWithFlags(&s2, cudaStreamNonBlocking);
        cudaEventCreateWithFlags(&evFork, cudaEventDisableTiming);
        cudaEventCreateWithFlags(&evJoin, cudaEventDisableTiming);
    }

    // fork: GEMM1 (x @ W1, + merged W2@Wc fold) is independent of edge structure
    cudaEventRecord(evFork, 0);
    cudaStreamWaitEvent(s2, evFork, 0);
    k_gemm<<<GEMM_BLOCKS + FUSE_BLOCKS, 256, 0, s2>>>(x, W1, d_h, W2, Wc, b2, bc);
    cudaEventRecord(evJoin, s2);

    // bucket build on main stream (concurrent with s2); counts arrive zeroed
    k_build<<<(EO + 255) / 256, 256>>>(ei);

    // join: scale needs both counts (build) and h (gemm1)
    cudaStreamWaitEvent(0, evJoin, 0);
    k_scale<<<(NN * FH / 8 + 255) / 256, 256>>>(d_h);

    // layer 1 aggregate + head projection into z rows
    k_agg1_proj<<<(NN + 15) / 16, 512>>>(d_h, b1, d_z);
    // layer 2 aggregate over z + log-softmax (also re-zeroes counts)
    k_agg2<<<(NN + 7) / 8, 256>>>(d_z, out);
}

// round 16
// speedup vs baseline: 1.1310x; 1.0844x over previous
#include <cuda_runtime.h>
#include <cuda_fp16.h>
#include <math.h>

// Problem constants (fixed shapes)
#define NN 10000
#define EE 640000
#define FH 128          // F_IN == H == 128
#define CC 40
#define ZW 64           // z row width in halves (40 real + pad) = 128 B
#define BKT 256         // bucket capacity per node (max degree ~110 for this dist)
#define EO (EE / 8)     // edges handled 8-per-thread in build
#define GEMM_BLOCKS 157 // ceil(10000/64)
#define FUSE_BLOCKS 20  // 5120 outputs / 256

typedef unsigned long long ull;

// ---------------- scratch (device globals; no allocation allowed) ----------------
// g_cnt is zero at process start (BSS) and re-zeroed at the end of k_agg2,
// so every kernel_launch execution sees zeroed counts (graph-replay safe).
// Row NN of g_h / g_z is a permanent zero row (never written): gather pad.
__device__ __align__(256) int    g_cnt[NN];             // in-degree counts (no self-loop)
__device__ __align__(256) int    g_bkt[NN * BKT];       // padded adjacency buckets (src ids)
__device__ __align__(256) __half g_h[(NN + 1) * FH];    // GEMM1 output (fp16), scaled in place
__device__ __align__(256) __half g_z[(NN + 1) * ZW];    // head-projected rows (fp16)
__device__ __align__(256) float  g_wf[FH * CC];         // Wfused = W2 @ Wc
__device__ __align__(256) float  g_bf[CC];              // bfused = b2 @ Wc + bc

// ---------------- packed f32x2 helpers (sm_103a) ----------------
__device__ __forceinline__ ull addf2(ull a, ull b) {
    ull r; asm("add.rn.f32x2 %0, %1, %2;" : "=l"(r) : "l"(a), "l"(b)); return r;
}
__device__ __forceinline__ ull h2tof2(unsigned int hv) {
    __half2 h = *reinterpret_cast<__half2*>(&hv);
    float2 f = __half22float2(h);
    ull r; asm("mov.b64 %0, {%1, %2};" : "=l"(r) : "f"(f.x), "f"(f.y)); return r;
}
__device__ __forceinline__ float2 unpackf2(ull a) {
    float2 f; asm("mov.b64 {%0, %1}, %2;" : "=f"(f.x), "=f"(f.y) : "l"(a)); return f;
}
__device__ __forceinline__ uint4 hadd2_v(uint4 a, uint4 b) {
    uint4 r;
    *(__half2*)&r.x = __hadd2(*(__half2*)&a.x, *(__half2*)&b.x);
    *(__half2*)&r.y = __hadd2(*(__half2*)&a.y, *(__half2*)&b.y);
    *(__half2*)&r.z = __hadd2(*(__half2*)&a.z, *(__half2*)&b.z);
    *(__half2*)&r.w = __hadd2(*(__half2*)&a.w, *(__half2*)&b.w);
    return r;
}
__device__ __forceinline__ int sel4(int4 v, int k) {
    return (k == 0) ? v.x : (k == 1) ? v.y : (k == 2) ? v.z : v.w;
}

// ---------------- kernel: bucket build (8 consecutive edges/thread, vector loads) ----------------
__global__ void k_build(const void* __restrict__ ei) {
    int t = blockIdx.x * blockDim.x + threadIdx.x;
    if (t >= EO) return;

    const int* __restrict__ w = (const int*)ei;
    bool is64 = true;
    #pragma unroll
    for (int j = 0; j < 8; j++)
        if (w[2 * j + 1] != 0) is64 = false;

    int s[8], d[8];
    if (!is64) {
        int4 sv0 = ((const int4*)w)[2 * t];
        int4 sv1 = ((const int4*)w)[2 * t + 1];
        int4 dv0 = ((const int4*)w)[EE / 4 + 2 * t];
        int4 dv1 = ((const int4*)w)[EE / 4 + 2 * t + 1];
        s[0] = sv0.x; s[1] = sv0.y; s[2] = sv0.z; s[3] = sv0.w;
        s[4] = sv1.x; s[5] = sv1.y; s[6] = sv1.z; s[7] = sv1.w;
        d[0] = dv0.x; d[1] = dv0.y; d[2] = dv0.z; d[3] = dv0.w;
        d[4] = dv1.x; d[5] = dv1.y; d[6] = dv1.z; d[7] = dv1.w;
    } else {
        const longlong2* __restrict__ L2s = (const longlong2*)ei;
        #pragma unroll
        for (int q = 0; q < 4; q++) {
            longlong2 a = L2s[4 * t + q];
            s[2 * q] = (int)a.x; s[2 * q + 1] = (int)a.y;
            longlong2 b = L2s[EE / 2 + 4 * t + q];
            d[2 * q] = (int)b.x; d[2 * q + 1] = (int)b.y;
        }
    }

    #pragma unroll
    for (int k = 0; k < 8; k++) {
        if ((unsigned)d[k] < NN && (unsigned)s[k] < NN) {
            int pos = atomicAdd(&g_cnt[d[k]], 1);
            if (pos < BKT - 4) g_bkt[d[k] * BKT + pos] = s[k];
        }
    }
}

// ---------------- GEMM (+ merged W2@Wc fold): C[M,128] = A[M,128] @ W[128,128], fp16 out ----------------
// R13-proven config: BM=64, BN=128, BK=32, 256 threads, 4x8 per thread.
__global__ void k_gemm(const float* __restrict__ A, const float* __restrict__ W,
                       __half* __restrict__ Cmat,
                       const float* __restrict__ W2, const float* __restrict__ Wc,
                       const float* __restrict__ b2, const float* __restrict__ bc) {
    if (blockIdx.x >= GEMM_BLOCKS) {
        int idx = (blockIdx.x - GEMM_BLOCKS) * 256 + threadIdx.x;
        if (idx < FH * CC) {
            int k = idx / CC, c = idx % CC;
            float acc = 0.0f;
            #pragma unroll 8
            for (int j = 0; j < FH; j++)
                acc = fmaf(W2[k * FH + j], Wc[j * CC + c], acc);
            g_wf[idx] = acc;
        }
        if (idx < CC) {
            float acc = bc[idx];
            #pragma unroll 8
            for (int j = 0; j < FH; j++)
                acc = fmaf(b2[j], Wc[j * CC + idx], acc);
            g_bf[idx] = acc;
        }
        return;
    }

    __shared__ float As[64][32];
    __shared__ float Bs[32][128];
    int tid = threadIdx.x;
    int tx = tid & 15;
    int ty = tid >> 4;
    int rowBase = blockIdx.x * 64;

    float acc[4][8];
    #pragma unroll
    for (int j = 0; j < 4; j++)
        #pragma unroll
        for (int i = 0; i < 8; i++) acc[j][i] = 0.0f;

    for (int k0 = 0; k0 < 128; k0 += 32) {
        #pragma unroll
        for (int p = 0; p < 2; p++) {
            int f = tid + p * 256;
            int r = f >> 3, c4 = f & 7;
            int grow = rowBase + r;
            float4 v = make_float4(0.f, 0.f, 0.f, 0.f);
            if (grow < NN)
                v = *(const float4*)&A[grow * 128 + k0 + c4 * 4];
            *(float4*)&As[r][c4 * 4] = v;
        }
        #pragma unroll
        for (int p = 0; p < 4; p++) {
            int f = tid + p * 256;
            int r = f >> 5, c4 = f & 31;
            float4 v = *(const float4*)&W[(k0 + r) * 128 + c4 * 4];
            *(float4*)&Bs[r][c4 * 4] = v;
        }
        __syncthreads();
        #pragma unroll
        for (int kk = 0; kk < 32; kk++) {
            float a[4];
            #pragma unroll
            for (int j = 0; j < 4; j++) a[j] = As[ty * 4 + j][kk];
            float4 b0 = *(float4*)&Bs[kk][tx * 8];
            float4 b1 = *(float4*)&Bs[kk][tx * 8 + 4];
            float b[8] = {b0.x, b0.y, b0.z, b0.w, b1.x, b1.y, b1.z, b1.w};
            #pragma unroll
            for (int j = 0; j < 4; j++)
                #pragma unroll
                for (int i = 0; i < 8; i++)
                    acc[j][i] = fmaf(a[j], b[i], acc[j][i]);
        }
        __syncthreads();
    }

    #pragma unroll
    for (int j = 0; j < 4; j++) {
        int row = rowBase + ty * 4 + j;
        if (row < NN) {
            uint4 o;
            *(__half2*)&o.x = __floats2half2_rn(acc[j][0], acc[j][1]);
            *(__half2*)&o.y = __floats2half2_rn(acc[j][2], acc[j][3]);
            *(__half2*)&o.z = __floats2half2_rn(acc[j][4], acc[j][5]);
            *(__half2*)&o.w = __floats2half2_rn(acc[j][6], acc[j][7]);
            *(uint4*)&Cmat[row * 128 + tx * 8] = o;
        }
    }
}

// ---------------- kernel: in-place row scaling h' = dinv(row) * h + bucket self/pad ----------------
// Bucket list becomes [neighbors..., self, pads...] with length a multiple of 4.
__global__ void k_scale(__half* __restrict__ h) {
    int i = blockIdx.x * blockDim.x + threadIdx.x;
    if (i < NN) {
        int n = g_cnt[i]; if (n > BKT - 4) n = BKT - 4;
        int p = i * BKT;
        g_bkt[p + n] = i;                  // self entry
        int mlen = n + 1;
        #pragma unroll
        for (int q = 0; q < 3; q++) {
            if (mlen & 3) { g_bkt[p + mlen] = NN; mlen++; }
        }
    }
    if (i >= NN * FH / 8) return;
    int row = i >> 4;
    float d = rsqrtf((float)(g_cnt[row] + 1));
    uint4 v = ((uint4*)h)[i];
    __half2* p = (__half2*)&v;
    #pragma unroll
    for (int k = 0; k < 4; k++) {
        float2 f = __half22float2(p[k]);
        p[k] = __floats2half2_rn(f.x * d, f.y * d);
    }
    ((uint4*)h)[i] = v;
}

// ---------------- shared accumulate step: 8 rows -> HADD2 pair-reduce -> fp32 ----------------
__device__ __forceinline__ void acc8(ull& a0, ull& a1, ull& a2, ull& a3,
                                     uint4 v0, uint4 v1, uint4 v2, uint4 v3,
                                     uint4 v4, uint4 v5, uint4 v6, uint4 v7) {
    uint4 p0 = hadd2_v(v0, v1);
    uint4 p1 = hadd2_v(v2, v3);
    uint4 p2 = hadd2_v(v4, v5);
    uint4 p3 = hadd2_v(v6, v7);
    a0 = addf2(a0, h2tof2(p0.x)); a1 = addf2(a1, h2tof2(p0.y));
    a2 = addf2(a2, h2tof2(p0.z)); a3 = addf2(a3, h2tof2(p0.w));
    a0 = addf2(a0, h2tof2(p1.x)); a1 = addf2(a1, h2tof2(p1.y));
    a2 = addf2(a2, h2tof2(p1.z)); a3 = addf2(a3, h2tof2(p1.w));
    a0 = addf2(a0, h2tof2(p2.x)); a1 = addf2(a1, h2tof2(p2.y));
    a2 = addf2(a2, h2tof2(p2.z)); a3 = addf2(a3, h2tof2(p2.w));
    a0 = addf2(a0, h2tof2(p3.x)); a1 = addf2(a1, h2tof2(p3.y));
    a2 = addf2(a2, h2tof2(p3.z)); a3 = addf2(a3, h2tof2(p3.w));
}

// ---------------- gather: plain, reg-lean (2 rows per LDG.128, HADD2 pre-reduce) ----------------
__device__ __forceinline__ void gather_plain(const __half* __restrict__ h,
                                             int node, int lane, int m,
                                             float out[8]) {
    int half = lane >> 4;
    int fl = lane & 15;
    const __half* __restrict__ rowoff = h + fl * 8;
    const int4* __restrict__ bp4 = (const int4*)&g_bkt[node * BKT];
    ull a0 = 0, a1 = 0, a2 = 0, a3 = 0;

    int e = 0;
    for (; e + 16 <= m; e += 16) {
        int4 iA = bp4[(e >> 2) + 0];
        int4 iB = bp4[(e >> 2) + 1];
        int4 iC = bp4[(e >> 2) + 2];
        int4 iD = bp4[(e >> 2) + 3];
        int s0 = half ? iA.y : iA.x;
        int s1 = half ? iA.w : iA.z;
        int s2 = half ? iB.y : iB.x;
        int s3 = half ? iB.w : iB.z;
        int s4 = half ? iC.y : iC.x;
        int s5 = half ? iC.w : iC.z;
        int s6 = half ? iD.y : iD.x;
        int s7 = half ? iD.w : iD.z;
        uint4 v0 = *(const uint4*)(rowoff + s0 * FH);
        uint4 v1 = *(const uint4*)(rowoff + s1 * FH);
        uint4 v2 = *(const uint4*)(rowoff + s2 * FH);
        uint4 v3 = *(const uint4*)(rowoff + s3 * FH);
        uint4 v4 = *(const uint4*)(rowoff + s4 * FH);
        uint4 v5 = *(const uint4*)(rowoff + s5 * FH);
        uint4 v6 = *(const uint4*)(rowoff + s6 * FH);
        uint4 v7 = *(const uint4*)(rowoff + s7 * FH);
        acc8(a0, a1, a2, a3, v0, v1, v2, v3, v4, v5, v6, v7);
    }
    const int* __restrict__ bp = (const int*)bp4;
    for (; e + 2 <= m; e += 2) {
        int s = bp[e + half];
        uint4 v = *(const uint4*)(rowoff + s * FH);
        a0 = addf2(a0, h2tof2(v.x)); a1 = addf2(a1, h2tof2(v.y));
        a2 = addf2(a2, h2tof2(v.z)); a3 = addf2(a3, h2tof2(v.w));
    }

    float2 f0 = unpackf2(a0), f1 = unpackf2(a1), f2 = unpackf2(a2), f3 = unpackf2(a3);
    out[0] = f0.x + __shfl_down_sync(0xFFFFFFFFu, f0.x, 16);
    out[1] = f0.y + __shfl_down_sync(0xFFFFFFFFu, f0.y, 16);
    out[2] = f1.x + __shfl_down_sync(0xFFFFFFFFu, f1.x, 16);
    out[3] = f1.y + __shfl_down_sync(0xFFFFFFFFu, f1.y, 16);
    out[4] = f2.x + __shfl_down_sync(0xFFFFFFFFu, f2.x, 16);
    out[5] = f2.y + __shfl_down_sync(0xFFFFFFFFu, f2.y, 16);
    out[6] = f3.x + __shfl_down_sync(0xFFFFFFFFu, f3.x, 16);
    out[7] = f3.y + __shfl_down_sync(0xFFFFFFFFu, f3.y, 16);
}

// ---------------- layer-1 agg + head projection (float2-paired matvec, R15-measured) ----------------
// 512 threads = 16 warps = 16 nodes per block; capped at 3 blocks/SM.
// z[node] = (dinv * relu(dinv*sum + b1)) @ Wf, stored as 64 fp16 (40 real + zero pad).
__global__ void __launch_bounds__(512, 3) k_agg1_proj(const __half* __restrict__ h,
                                                      const float* __restrict__ bias,
                                                      __half* __restrict__ z) {
    __shared__ float2 Wf2s[64 * CC];     // k-paired Wf: 20.5 KB
    __shared__ float2 hrow2[16 * 64];    // k-paired h1 rows: 8 KB

    int tid = threadIdx.x;
    int lane = tid & 31;
    int w = tid >> 5;
    for (int i = tid; i < 64 * CC; i += 512) {
        int k2 = i / CC, c = i - k2 * CC;
        Wf2s[i] = make_float2(g_wf[(2 * k2) * CC + c], g_wf[(2 * k2 + 1) * CC + c]);
    }
    __syncthreads();

    int node = blockIdx.x * 16 + w;
    if (node >= NN) return;

    int n = g_cnt[node]; if (n > BKT - 4) n = BKT - 4;
    int m = (n + 4) & ~3;
    float di = rsqrtf((float)(n + 1));
    float f[8];
    gather_plain(h, node, lane, m, f);
    if (lane < 16) {
        float4 b0 = *(const float4*)&bias[lane * 8];
        float4 b1 = *(const float4*)&bias[lane * 8 + 4];
        float bb[8] = {b0.x, b0.y, b0.z, b0.w, b1.x, b1.y, b1.z, b1.w};
        float r[8];
        #pragma unroll
        for (int k = 0; k < 8; k++)
            r[k] = di * fmaxf(fmaf(f[k], di, bb[k]), 0.f);
        // lane covers k = 8*lane..8*lane+7 -> float2 pairs k2 = 4*lane..4*lane+3
        float4 o0 = make_float4(r[0], r[1], r[2], r[3]);
        float4 o1 = make_float4(r[4], r[5], r[6], r[7]);
        *(float4*)&hrow2[w * 64 + 4 * lane]     = o0;   // 2 float2s
        *(float4*)&hrow2[w * 64 + 4 * lane + 2] = o1;   // 2 float2s
    }
    __syncwarp();

    // head projection: z_c = sum_k2 hrow2[k2] . Wf2[k2][c]; lane handles c0=lane, c1=lane+32
    int c0 = lane;
    int c1 = lane + 32;
    float z0 = 0.0f, z1 = 0.0f;
    const float2* __restrict__ hp = &hrow2[w * 64];
    #pragma unroll 4
    for (int k2 = 0; k2 < 64; k2++) {
        float2 hv = hp[k2];
        float2 wa = Wf2s[k2 * CC + c0];
        z0 = fmaf(hv.x, wa.x, z0);
        z0 = fmaf(hv.y, wa.y, z0);
        if (c1 < CC) {
            float2 wb = Wf2s[k2 * CC + c1];
            z1 = fmaf(hv.x, wb.x, z1);
            z1 = fmaf(hv.y, wb.y, z1);
        }
    }
    // z row = 64 halves: [0..39] real, [40..63] zero
    z[node * ZW + lane] = __float2half(z0);
    z[node * ZW + 32 + lane] = (c1 < CC) ? __float2half(z1) : __half(0.0f);
}

// ---------------- layer-2 agg over z rows (128 B each, 4 rows per LDG.128) + log-softmax ----------------
// 256 threads = 8 warps = 8 nodes per block.
__global__ void __launch_bounds__(256) k_agg2(const __half* __restrict__ z,
                                              float* __restrict__ out) {
    int tid = threadIdx.x;
    int lane = tid & 31;
    int node = blockIdx.x * 8 + (tid >> 5);
    if (node >= NN) return;

    int n = g_cnt[node]; if (n > BKT - 4) n = BKT - 4;
    int m = (n + 4) & ~3;
    float di = rsqrtf((float)(n + 1));

    int rsel = lane >> 3;          // which of 4 rows in a group
    int chunk = lane & 7;          // 8-half feature chunk
    const __half* __restrict__ zoff = z + chunk * 8;
    const int4* __restrict__ bp4 = (const int4*)&g_bkt[node * BKT];
    ull a0 = 0, a1 = 0, a2 = 0, a3 = 0;

    int e = 0;
    for (; e + 16 <= m; e += 16) {
        int4 iA = bp4[(e >> 2) + 0];
        int4 iB = bp4[(e >> 2) + 1];
        int4 iC = bp4[(e >> 2) + 2];
        int4 iD = bp4[(e >> 2) + 3];
        int s0 = sel4(iA, rsel);
        int s1 = sel4(iB, rsel);
        int s2 = sel4(iC, rsel);
        int s3 = sel4(iD, rsel);
        uint4 v0 = *(const uint4*)(zoff + s0 * ZW);
        uint4 v1 = *(const uint4*)(zoff + s1 * ZW);
        uint4 v2 = *(const uint4*)(zoff + s2 * ZW);
        uint4 v3 = *(const uint4*)(zoff + s3 * ZW);
        uint4 p0 = hadd2_v(v0, v1);
        uint4 p1 = hadd2_v(v2, v3);
        a0 = addf2(a0, h2tof2(p0.x)); a1 = addf2(a1, h2tof2(p0.y));
        a2 = addf2(a2, h2tof2(p0.z)); a3 = addf2(a3, h2tof2(p0.w));
        a0 = addf2(a0, h2tof2(p1.x)); a1 = addf2(a1, h2tof2(p1.y));
        a2 = addf2(a2, h2tof2(p1.z)); a3 = addf2(a3, h2tof2(p1.w));
    }
    const int* __restrict__ bp = (const int*)bp4;
    for (; e + 4 <= m; e += 4) {
        int s = bp[e + rsel];
        uint4 v = *(const uint4*)(zoff + s * ZW);
        a0 = addf2(a0, h2tof2(v.x)); a1 = addf2(a1, h2tof2(v.y));
        a2 = addf2(a2, h2tof2(v.z)); a3 = addf2(a3, h2tof2(v.w));
    }

    // combine row groups: lanes {l, l+8, l+16, l+24} hold same feature chunk
    float2 f0 = unpackf2(a0), f1 = unpackf2(a1), f2 = unpackf2(a2), f3 = unpackf2(a3);
    float v[8] = {f0.x, f0.y, f1.x, f1.y, f2.x, f2.y, f3.x, f3.y};
    #pragma unroll
    for (int j = 0; j < 8; j++) {
        v[j] += __shfl_down_sync(0xFFFFFFFFu, v[j], 16);
        v[j] += __shfl_down_sync(0xFFFFFFFFu, v[j], 8);
    }
    // lanes 0-7: chunk = lane, features base = lane*8
    int base = lane * 8;
    float lg[8];
    #pragma unroll
    for (int j = 0; j < 8; j++) {
        int c = base + j;
        lg[j] = (c < CC) ? fmaf(v[j], di, g_bf[c]) : -1e30f;
    }

    // reset count for the next graph replay (last reader of g_cnt)
    if (lane == 0) g_cnt[node] = 0;

    // log-softmax across lanes 0-7 (butterfly within group of 8)
    float mx = lg[0];
    #pragma unroll
    for (int j = 1; j < 8; j++) mx = fmaxf(mx, lg[j]);
    #pragma unroll
    for (int o = 4; o > 0; o >>= 1)
        mx = fmaxf(mx, __shfl_xor_sync(0xFFFFFFFFu, mx, o));
    float s = 0.0f;
    #pragma unroll
    for (int j = 0; j < 8; j++)
        if (base + j < CC) s += __expf(lg[j] - mx);
    #pragma unroll
    for (int o = 4; o > 0; o >>= 1)
        s += __shfl_xor_sync(0xFFFFFFFFu, s, o);
    float lse = mx + __logf(s);

    if (base < CC) {
        float4 o0 = make_float4(lg[0] - lse, lg[1] - lse, lg[2] - lse, lg[3] - lse);
        float4 o1 = make_float4(lg[4] - lse, lg[5] - lse, lg[6] - lse, lg[7] - lse);
        *(float4*)&out[node * CC + base]     = o0;
        *(float4*)&out[node * CC + base + 4] = o1;
    }
}

// ---------------- launch ----------------
extern "C" void kernel_launch(void* const* d_in, const int* in_sizes, int n_in,
                              void* d_out, int out_size) {
    const float* x   = (const float*)d_in[0];
    const void*  ei  = d_in[1];
    const float* W1  = (const float*)d_in[2];
    const float* b1  = (const float*)d_in[3];
    const float* W2  = (const float*)d_in[4];
    const float* b2  = (const float*)d_in[5];
    const float* Wc  = (const float*)d_in[6];
    const float* bc  = (const float*)d_in[7];
    float* out = (float*)d_out;

    __half* d_h; cudaGetSymbolAddress((void**)&d_h, g_h);
    __half* d_z; cudaGetSymbolAddress((void**)&d_z, g_z);

    static cudaStream_t s2 = nullptr;
    static cudaEvent_t evFork = nullptr, evJoin = nullptr;
    if (!s2) {
        cudaStreamCreateWithFlags(&s2, cudaStreamNonBlocking);
        cudaEventCreateWithFlags(&evFork, cudaEventDisableTiming);
        cudaEventCreateWithFlags(&evJoin, cudaEventDisableTiming);
    }

    // fork: GEMM1 (x @ W1, + merged W2@Wc fold) is independent of edge structure
    cudaEventRecord(evFork, 0);
    cudaStreamWaitEvent(s2, evFork, 0);
    k_gemm<<<GEMM_BLOCKS + FUSE_BLOCKS, 256, 0, s2>>>(x, W1, d_h, W2, Wc, b2, bc);
    cudaEventRecord(evJoin, s2);

    // bucket build on main stream (concurrent with s2); counts arrive zeroed
    k_build<<<(EO + 255) / 256, 256>>>(ei);

    // join: scale needs both counts (build) and h (gemm1)
    cudaStreamWaitEvent(0, evJoin, 0);
    k_scale<<<(NN * FH / 8 + 255) / 256, 256>>>(d_h);

    // layer 1 aggregate + head projection into z rows
    k_agg1_proj<<<(NN + 15) / 16, 512>>>(d_h, b1, d_z);
    // layer 2 aggregate over z + log-softmax (also re-zeroes counts)
    k_agg2<<<(NN + 7) / 8, 256>>>(d_z, out);
}

// round 17
// speedup vs baseline: 1.1874x; 1.0498x over previous
#include <cuda_runtime.h>
#include <cuda_fp16.h>
#include <math.h>

// Problem constants (fixed shapes)
#define NN 10000
#define EE 640000
#define FH 128          // F_IN == H == 128
#define CC 40
#define ZW 64           // z row width in halves (40 real + pad) = 128 B
#define BKT 256         // bucket capacity per node (max degree ~110 for this dist)
#define EO (EE / 8)     // edges handled 8-per-thread in build
#define GEMM_BLOCKS 157 // ceil(10000/64)
#define FUSE_BLOCKS 20  // 5120 outputs / 256

typedef unsigned long long ull;

// ---------------- scratch (device globals; no allocation allowed) ----------------
// g_cnt is zero at process start (BSS) and re-zeroed at the end of k_agg2,
// so every kernel_launch execution sees zeroed counts (graph-replay safe).
// Row NN of g_h / g_z is a permanent zero row (never written): gather pad.
__device__ __align__(256) int    g_cnt[NN];             // in-degree counts (no self-loop)
__device__ __align__(256) int    g_bkt[NN * BKT];       // padded adjacency buckets (src ids)
__device__ __align__(256) __half g_h[(NN + 1) * FH];    // GEMM1 output (fp16), scaled in place
__device__ __align__(256) __half g_z[(NN + 1) * ZW];    // head-projected rows (fp16)
__device__ __align__(256) float  g_wf[FH * CC];         // Wfused = W2 @ Wc
__device__ __align__(256) float  g_bf[CC];              // bfused = b2 @ Wc + bc

// ---------------- packed f32x2 helpers (sm_103a) ----------------
__device__ __forceinline__ ull addf2(ull a, ull b) {
    ull r; asm("add.rn.f32x2 %0, %1, %2;" : "=l"(r) : "l"(a), "l"(b)); return r;
}
__device__ __forceinline__ ull fmaf2(ull a, ull b, ull c) {
    ull r; asm("fma.rn.f32x2 %0, %1, %2, %3;" : "=l"(r) : "l"(a), "l"(b), "l"(c)); return r;
}
__device__ __forceinline__ ull packf2(float x, float y) {
    ull r; asm("mov.b64 %0, {%1, %2};" : "=l"(r) : "f"(x), "f"(y)); return r;
}
__device__ __forceinline__ ull h2tof2(unsigned int hv) {
    __half2 h = *reinterpret_cast<__half2*>(&hv);
    float2 f = __half22float2(h);
    ull r; asm("mov.b64 %0, {%1, %2};" : "=l"(r) : "f"(f.x), "f"(f.y)); return r;
}
__device__ __forceinline__ float2 unpackf2(ull a) {
    float2 f; asm("mov.b64 {%0, %1}, %2;" : "=f"(f.x), "=f"(f.y) : "l"(a)); return f;
}
__device__ __forceinline__ uint4 hadd2_v(uint4 a, uint4 b) {
    uint4 r;
    *(__half2*)&r.x = __hadd2(*(__half2*)&a.x, *(__half2*)&b.x);
    *(__half2*)&r.y = __hadd2(*(__half2*)&a.y, *(__half2*)&b.y);
    *(__half2*)&r.z = __hadd2(*(__half2*)&a.z, *(__half2*)&b.z);
    *(__half2*)&r.w = __hadd2(*(__half2*)&a.w, *(__half2*)&b.w);
    return r;
}
__device__ __forceinline__ int sel4(int4 v, int k) {
    return (k == 0) ? v.x : (k == 1) ? v.y : (k == 2) ? v.z : v.w;
}

// ---------------- kernel: bucket build (8 consecutive edges/thread, vector loads) ----------------
__global__ void k_build(const void* __restrict__ ei) {
    int t = blockIdx.x * blockDim.x + threadIdx.x;
    if (t >= EO) return;

    const int* __restrict__ w = (const int*)ei;
    bool is64 = true;
    #pragma unroll
    for (int j = 0; j < 8; j++)
        if (w[2 * j + 1] != 0) is64 = false;

    int s[8], d[8];
    if (!is64) {
        int4 sv0 = ((const int4*)w)[2 * t];
        int4 sv1 = ((const int4*)w)[2 * t + 1];
        int4 dv0 = ((const int4*)w)[EE / 4 + 2 * t];
        int4 dv1 = ((const int4*)w)[EE / 4 + 2 * t + 1];
        s[0] = sv0.x; s[1] = sv0.y; s[2] = sv0.z; s[3] = sv0.w;
        s[4] = sv1.x; s[5] = sv1.y; s[6] = sv1.z; s[7] = sv1.w;
        d[0] = dv0.x; d[1] = dv0.y; d[2] = dv0.z; d[3] = dv0.w;
        d[4] = dv1.x; d[5] = dv1.y; d[6] = dv1.z; d[7] = dv1.w;
    } else {
        const longlong2* __restrict__ L2s = (const longlong2*)ei;
        #pragma unroll
        for (int q = 0; q < 4; q++) {
            longlong2 a = L2s[4 * t + q];
            s[2 * q] = (int)a.x; s[2 * q + 1] = (int)a.y;
            longlong2 b = L2s[EE / 2 + 4 * t + q];
            d[2 * q] = (int)b.x; d[2 * q + 1] = (int)b.y;
        }
    }

    #pragma unroll
    for (int k = 0; k < 8; k++) {
        if ((unsigned)d[k] < NN && (unsigned)s[k] < NN) {
            int pos = atomicAdd(&g_cnt[d[k]], 1);
            if (pos < BKT - 4) g_bkt[d[k] * BKT + pos] = s[k];
        }
    }
}

// ---------------- GEMM (+ merged W2@Wc fold): C[M,128] = A[M,128] @ W[128,128], fp16 out ----------------
// R13 tiling (BM=64, BN=128, BK=32, 256 threads, 4x8/thread) with f32x2 packed FMA.
__global__ void k_gemm(const float* __restrict__ A, const float* __restrict__ W,
                       __half* __restrict__ Cmat,
                       const float* __restrict__ W2, const float* __restrict__ Wc,
                       const float* __restrict__ b2, const float* __restrict__ bc) {
    if (blockIdx.x >= GEMM_BLOCKS) {
        int idx = (blockIdx.x - GEMM_BLOCKS) * 256 + threadIdx.x;
        if (idx < FH * CC) {
            int k = idx / CC, c = idx % CC;
            float acc = 0.0f;
            #pragma unroll 8
            for (int j = 0; j < FH; j++)
                acc = fmaf(W2[k * FH + j], Wc[j * CC + c], acc);
            g_wf[idx] = acc;
        }
        if (idx < CC) {
            float acc = bc[idx];
            #pragma unroll 8
            for (int j = 0; j < FH; j++)
                acc = fmaf(b2[j], Wc[j * CC + idx], acc);
            g_bf[idx] = acc;
        }
        return;
    }

    __shared__ float As[64][32];
    __shared__ float Bs[32][128];
    int tid = threadIdx.x;
    int tx = tid & 15;
    int ty = tid >> 4;
    int rowBase = blockIdx.x * 64;

    ull acc2[4][4];      // 4 rows x 4 column-pairs (8 columns)
    #pragma unroll
    for (int j = 0; j < 4; j++)
        #pragma unroll
        for (int i = 0; i < 4; i++) acc2[j][i] = 0ULL;

    for (int k0 = 0; k0 < 128; k0 += 32) {
        #pragma unroll
        for (int p = 0; p < 2; p++) {
            int f = tid + p * 256;
            int r = f >> 3, c4 = f & 7;
            int grow = rowBase + r;
            float4 v = make_float4(0.f, 0.f, 0.f, 0.f);
            if (grow < NN)
                v = *(const float4*)&A[grow * 128 + k0 + c4 * 4];
            *(float4*)&As[r][c4 * 4] = v;
        }
        #pragma unroll
        for (int p = 0; p < 4; p++) {
            int f = tid + p * 256;
            int r = f >> 5, c4 = f & 31;
            float4 v = *(const float4*)&W[(k0 + r) * 128 + c4 * 4];
            *(float4*)&Bs[r][c4 * 4] = v;
        }
        __syncthreads();
        #pragma unroll
        for (int kk = 0; kk < 32; kk++) {
            ull a2[4];
            #pragma unroll
            for (int j = 0; j < 4; j++) {
                float a = As[ty * 4 + j][kk];
                a2[j] = packf2(a, a);
            }
            const ull* __restrict__ brow = (const ull*)&Bs[kk][tx * 8];
            ull b0 = brow[0], b1 = brow[1], b2v = brow[2], b3 = brow[3];
            #pragma unroll
            for (int j = 0; j < 4; j++) {
                acc2[j][0] = fmaf2(a2[j], b0, acc2[j][0]);
                acc2[j][1] = fmaf2(a2[j], b1, acc2[j][1]);
                acc2[j][2] = fmaf2(a2[j], b2v, acc2[j][2]);
                acc2[j][3] = fmaf2(a2[j], b3, acc2[j][3]);
            }
        }
        __syncthreads();
    }

    #pragma unroll
    for (int j = 0; j < 4; j++) {
        int row = rowBase + ty * 4 + j;
        if (row < NN) {
            uint4 o;
            float2 p0 = unpackf2(acc2[j][0]);
            float2 p1 = unpackf2(acc2[j][1]);
            float2 p2 = unpackf2(acc2[j][2]);
            float2 p3 = unpackf2(acc2[j][3]);
            *(__half2*)&o.x = __floats2half2_rn(p0.x, p0.y);
            *(__half2*)&o.y = __floats2half2_rn(p1.x, p1.y);
            *(__half2*)&o.z = __floats2half2_rn(p2.x, p2.y);
            *(__half2*)&o.w = __floats2half2_rn(p3.x, p3.y);
            *(uint4*)&Cmat[row * 128 + tx * 8] = o;
        }
    }
}

// ---------------- kernel: in-place row scaling h' = dinv(row) * h + bucket self/pad ----------------
// Bucket list becomes [neighbors..., self, pads...] with length a multiple of 4.
__global__ void k_scale(__half* __restrict__ h) {
    int i = blockIdx.x * blockDim.x + threadIdx.x;
    if (i < NN) {
        int n = g_cnt[i]; if (n > BKT - 4) n = BKT - 4;
        int p = i * BKT;
        g_bkt[p + n] = i;                  // self entry
        int mlen = n + 1;
        #pragma unroll
        for (int q = 0; q < 3; q++) {
            if (mlen & 3) { g_bkt[p + mlen] = NN; mlen++; }
        }
    }
    if (i >= NN * FH / 8) return;
    int row = i >> 4;
    float d = rsqrtf((float)(g_cnt[row] + 1));
    uint4 v = ((uint4*)h)[i];
    __half2* p = (__half2*)&v;
    #pragma unroll
    for (int k = 0; k < 4; k++) {
        float2 f = __half22float2(p[k]);
        p[k] = __floats2half2_rn(f.x * d, f.y * d);
    }
    ((uint4*)h)[i] = v;
}

// ---------------- shared accumulate step: 8 rows -> HADD2 pair-reduce -> fp32 ----------------
__device__ __forceinline__ void acc8(ull& a0, ull& a1, ull& a2, ull& a3,
                                     uint4 v0, uint4 v1, uint4 v2, uint4 v3,
                                     uint4 v4, uint4 v5, uint4 v6, uint4 v7) {
    uint4 p0 = hadd2_v(v0, v1);
    uint4 p1 = hadd2_v(v2, v3);
    uint4 p2 = hadd2_v(v4, v5);
    uint4 p3 = hadd2_v(v6, v7);
    a0 = addf2(a0, h2tof2(p0.x)); a1 = addf2(a1, h2tof2(p0.y));
    a2 = addf2(a2, h2tof2(p0.z)); a3 = addf2(a3, h2tof2(p0.w));
    a0 = addf2(a0, h2tof2(p1.x)); a1 = addf2(a1, h2tof2(p1.y));
    a2 = addf2(a2, h2tof2(p1.z)); a3 = addf2(a3, h2tof2(p1.w));
    a0 = addf2(a0, h2tof2(p2.x)); a1 = addf2(a1, h2tof2(p2.y));
    a2 = addf2(a2, h2tof2(p2.z)); a3 = addf2(a3, h2tof2(p2.w));
    a0 = addf2(a0, h2tof2(p3.x)); a1 = addf2(a1, h2tof2(p3.y));
    a2 = addf2(a2, h2tof2(p3.z)); a3 = addf2(a3, h2tof2(p3.w));
}

// ---------------- gather: plain, reg-lean (2 rows per LDG.128, HADD2 pre-reduce) ----------------
__device__ __forceinline__ void gather_plain(const __half* __restrict__ h,
                                             int node, int lane, int m,
                                             float out[8]) {
    int half = lane >> 4;
    int fl = lane & 15;
    const __half* __restrict__ rowoff = h + fl * 8;
    const int4* __restrict__ bp4 = (const int4*)&g_bkt[node * BKT];
    ull a0 = 0, a1 = 0, a2 = 0, a3 = 0;

    int e = 0;
    for (; e + 16 <= m; e += 16) {
        int4 iA = bp4[(e >> 2) + 0];
        int4 iB = bp4[(e >> 2) + 1];
        int4 iC = bp4[(e >> 2) + 2];
        int4 iD = bp4[(e >> 2) + 3];
        int s0 = half ? iA.y : iA.x;
        int s1 = half ? iA.w : iA.z;
        int s2 = half ? iB.y : iB.x;
        int s3 = half ? iB.w : iB.z;
        int s4 = half ? iC.y : iC.x;
        int s5 = half ? iC.w : iC.z;
        int s6 = half ? iD.y : iD.x;
        int s7 = half ? iD.w : iD.z;
        uint4 v0 = *(const uint4*)(rowoff + s0 * FH);
        uint4 v1 = *(const uint4*)(rowoff + s1 * FH);
        uint4 v2 = *(const uint4*)(rowoff + s2 * FH);
        uint4 v3 = *(const uint4*)(rowoff + s3 * FH);
        uint4 v4 = *(const uint4*)(rowoff + s4 * FH);
        uint4 v5 = *(const uint4*)(rowoff + s5 * FH);
        uint4 v6 = *(const uint4*)(rowoff + s6 * FH);
        uint4 v7 = *(const uint4*)(rowoff + s7 * FH);
        acc8(a0, a1, a2, a3, v0, v1, v2, v3, v4, v5, v6, v7);
    }
    const int* __restrict__ bp = (const int*)bp4;
    for (; e + 2 <= m; e += 2) {
        int s = bp[e + half];
        uint4 v = *(const uint4*)(rowoff + s * FH);
        a0 = addf2(a0, h2tof2(v.x)); a1 = addf2(a1, h2tof2(v.y));
        a2 = addf2(a2, h2tof2(v.z)); a3 = addf2(a3, h2tof2(v.w));
    }

    float2 f0 = unpackf2(a0), f1 = unpackf2(a1), f2 = unpackf2(a2), f3 = unpackf2(a3);
    out[0] = f0.x + __shfl_down_sync(0xFFFFFFFFu, f0.x, 16);
    out[1] = f0.y + __shfl_down_sync(0xFFFFFFFFu, f0.y, 16);
    out[2] = f1.x + __shfl_down_sync(0xFFFFFFFFu, f1.x, 16);
    out[3] = f1.y + __shfl_down_sync(0xFFFFFFFFu, f1.y, 16);
    out[4] = f2.x + __shfl_down_sync(0xFFFFFFFFu, f2.x, 16);
    out[5] = f2.y + __shfl_down_sync(0xFFFFFFFFu, f2.y, 16);
    out[6] = f3.x + __shfl_down_sync(0xFFFFFFFFu, f3.x, 16);
    out[7] = f3.y + __shfl_down_sync(0xFFFFFFFFu, f3.y, 16);
}

// ---------------- layer-1 agg + head projection (f32x2 FFMA2 matvec) ----------------
// 512 threads = 16 warps = 16 nodes per block; capped at 3 blocks/SM.
// z[node] = (dinv * relu(dinv*sum + b1)) @ Wf, stored as 64 fp16 (40 real + zero pad).
__global__ void __launch_bounds__(512, 3) k_agg1_proj(const __half* __restrict__ h,
                                                      const float* __restrict__ bias,
                                                      __half* __restrict__ z) {
    __shared__ ull Wf2s[64 * CC];     // k-paired Wf: 20.5 KB
    __shared__ ull hrow2[16 * 64];    // k-paired h1 rows: 8 KB

    int tid = threadIdx.x;
    int lane = tid & 31;
    int w = tid >> 5;
    for (int i = tid; i < 64 * CC; i += 512) {
        int k2 = i / CC, c = i - k2 * CC;
        Wf2s[i] = packf2(g_wf[(2 * k2) * CC + c], g_wf[(2 * k2 + 1) * CC + c]);
    }
    __syncthreads();

    int node = blockIdx.x * 16 + w;
    if (node >= NN) return;

    int n = g_cnt[node]; if (n > BKT - 4) n = BKT - 4;
    int m = (n + 4) & ~3;
    float di = rsqrtf((float)(n + 1));
    float f[8];
    gather_plain(h, node, lane, m, f);
    if (lane < 16) {
        float4 b0 = *(const float4*)&bias[lane * 8];
        float4 b1 = *(const float4*)&bias[lane * 8 + 4];
        float bb[8] = {b0.x, b0.y, b0.z, b0.w, b1.x, b1.y, b1.z, b1.w};
        float r[8];
        #pragma unroll
        for (int k = 0; k < 8; k++)
            r[k] = di * fmaxf(fmaf(f[k], di, bb[k]), 0.f);
        // lane covers k = 8*lane..8*lane+7 -> pairs k2 = 4*lane..4*lane+3
        float4 o0 = make_float4(r[0], r[1], r[2], r[3]);
        float4 o1 = make_float4(r[4], r[5], r[6], r[7]);
        *(float4*)&hrow2[w * 64 + 4 * lane]     = o0;   // 2 ull pairs
        *(float4*)&hrow2[w * 64 + 4 * lane + 2] = o1;   // 2 ull pairs
    }
    __syncwarp();

    // head projection: z_c = sum_k2 hrow2[k2] . Wf2[k2][c]; lane handles c0=lane, c1=lane+32
    int c0 = lane;
    int c1 = lane + 32;
    ull z0p = 0, z1p = 0;
    const ull* __restrict__ hp = &hrow2[w * 64];
    #pragma unroll 4
    for (int k2 = 0; k2 < 64; k2++) {
        ull hv = hp[k2];
        z0p = fmaf2(hv, Wf2s[k2 * CC + c0], z0p);
        if (c1 < CC) z1p = fmaf2(hv, Wf2s[k2 * CC + c1], z1p);
    }
    float2 t0 = unpackf2(z0p);
    float2 t1 = unpackf2(z1p);
    float z0 = t0.x + t0.y;
    float z1 = t1.x + t1.y;
    // z row = 64 halves: [0..39] real, [40..63] zero
    z[node * ZW + lane] = __float2half(z0);
    z[node * ZW + 32 + lane] = (c1 < CC) ? __float2half(z1) : __half(0.0f);
}

// ---------------- layer-2 agg over z rows (128 B each, 4 rows per LDG.128) + log-softmax ----------------
// 256 threads = 8 warps = 8 nodes per block.
__global__ void __launch_bounds__(256) k_agg2(const __half* __restrict__ z,
                                              float* __restrict__ out) {
    int tid = threadIdx.x;
    int lane = tid & 31;
    int node = blockIdx.x * 8 + (tid >> 5);
    if (node >= NN) return;

    int n = g_cnt[node]; if (n > BKT - 4) n = BKT - 4;
    int m = (n + 4) & ~3;
    float di = rsqrtf((float)(n + 1));

    int rsel = lane >> 3;          // which of 4 rows in a group
    int chunk = lane & 7;          // 8-half feature chunk
    const __half* __restrict__ zoff = z + chunk * 8;
    const int4* __restrict__ bp4 = (const int4*)&g_bkt[node * BKT];
    ull a0 = 0, a1 = 0, a2 = 0, a3 = 0;

    int e = 0;
    for (; e + 16 <= m; e += 16) {
        int4 iA = bp4[(e >> 2) + 0];
        int4 iB = bp4[(e >> 2) + 1];
        int4 iC = bp4[(e >> 2) + 2];
        int4 iD = bp4[(e >> 2) + 3];
        int s0 = sel4(iA, rsel);
        int s1 = sel4(iB, rsel);
        int s2 = sel4(iC, rsel);
        int s3 = sel4(iD, rsel);
        uint4 v0 = *(const uint4*)(zoff + s0 * ZW);
        uint4 v1 = *(const uint4*)(zoff + s1 * ZW);
        uint4 v2 = *(const uint4*)(zoff + s2 * ZW);
        uint4 v3 = *(const uint4*)(zoff + s3 * ZW);
        uint4 p0 = hadd2_v(v0, v1);
        uint4 p1 = hadd2_v(v2, v3);
        a0 = addf2(a0, h2tof2(p0.x)); a1 = addf2(a1, h2tof2(p0.y));
        a2 = addf2(a2, h2tof2(p0.z)); a3 = addf2(a3, h2tof2(p0.w));
        a0 = addf2(a0, h2tof2(p1.x)); a1 = addf2(a1, h2tof2(p1.y));
        a2 = addf2(a2, h2tof2(p1.z)); a3 = addf2(a3, h2tof2(p1.w));
    }
    const int* __restrict__ bp = (const int*)bp4;
    for (; e + 4 <= m; e += 4) {
        int s = bp[e + rsel];
        uint4 v = *(const uint4*)(zoff + s * ZW);
        a0 = addf2(a0, h2tof2(v.x)); a1 = addf2(a1, h2tof2(v.y));
        a2 = addf2(a2, h2tof2(v.z)); a3 = addf2(a3, h2tof2(v.w));
    }

    // combine row groups: lanes {l, l+8, l+16, l+24} hold same feature chunk
    float2 f0 = unpackf2(a0), f1 = unpackf2(a1), f2 = unpackf2(a2), f3 = unpackf2(a3);
    float v[8] = {f0.x, f0.y, f1.x, f1.y, f2.x, f2.y, f3.x, f3.y};
    #pragma unroll
    for (int j = 0; j < 8; j++) {
        v[j] += __shfl_down_sync(0xFFFFFFFFu, v[j], 16);
        v[j] += __shfl_down_sync(0xFFFFFFFFu, v[j], 8);
    }
    // lanes 0-7: chunk = lane, features base = lane*8
    int base = lane * 8;
    float lg[8];
    #pragma unroll
    for (int j = 0; j < 8; j++) {
        int c = base + j;
        lg[j] = (c < CC) ? fmaf(v[j], di, g_bf[c]) : -1e30f;
    }

    // reset count for the next graph replay (last reader of g_cnt)
    if (lane == 0) g_cnt[node] = 0;

    // log-softmax across lanes 0-7 (butterfly within group of 8)
    float mx = lg[0];
    #pragma unroll
    for (int j = 1; j < 8; j++) mx = fmaxf(mx, lg[j]);
    #pragma unroll
    for (int o = 4; o > 0; o >>= 1)
        mx = fmaxf(mx, __shfl_xor_sync(0xFFFFFFFFu, mx, o));
    float s = 0.0f;
    #pragma unroll
    for (int j = 0; j < 8; j++)
        if (base + j < CC) s += __expf(lg[j] - mx);
    #pragma unroll
    for (int o = 4; o > 0; o >>= 1)
        s += __shfl_xor_sync(0xFFFFFFFFu, s, o);
    float lse = mx + __logf(s);

    if (base < CC) {
        float4 o0 = make_float4(lg[0] - lse, lg[1] - lse, lg[2] - lse, lg[3] - lse);
        float4 o1 = make_float4(lg[4] - lse, lg[5] - lse, lg[6] - lse, lg[7] - lse);
        *(float4*)&out[node * CC + base]     = o0;
        *(float4*)&out[node * CC + base + 4] = o1;
    }
}

// ---------------- launch ----------------
extern "C" void kernel_launch(void* const* d_in, const int* in_sizes, int n_in,
                              void* d_out, int out_size) {
    const float* x   = (const float*)d_in[0];
    const void*  ei  = d_in[1];
    const float* W1  = (const float*)d_in[2];
    const float* b1  = (const float*)d_in[3];
    const float* W2  = (const float*)d_in[4];
    const float* b2  = (const float*)d_in[5];
    const float* Wc  = (const float*)d_in[6];
    const float* bc  = (const float*)d_in[7];
    float* out = (float*)d_out;

    __half* d_h; cudaGetSymbolAddress((void**)&d_h, g_h);
    __half* d_z; cudaGetSymbolAddress((void**)&d_z, g_z);

    static cudaStream_t s2 = nullptr;
    static cudaEvent_t evFork = nullptr, evJoin = nullptr;
    if (!s2) {
        cudaStreamCreateWithFlags(&s2, cudaStreamNonBlocking);
        cudaEventCreateWithFlags(&evFork, cudaEventDisableTiming);
        cudaEventCreateWithFlags(&evJoin, cudaEventDisableTiming);
    }

    // fork: GEMM1 (x @ W1, + merged W2@Wc fold) is independent of edge structure
    cudaEventRecord(evFork, 0);
    cudaStreamWaitEvent(s2, evFork, 0);
    k_gemm<<<GEMM_BLOCKS + FUSE_BLOCKS, 256, 0, s2>>>(x, W1, d_h, W2, Wc, b2, bc);
    cudaEventRecord(evJoin, s2);

    // bucket build on main stream (concurrent with s2); counts arrive zeroed
    k_build<<<(EO + 255) / 256, 256>>>(ei);

    // join: scale needs both counts (build) and h (gemm1)
    cudaStreamWaitEvent(0, evJoin, 0);
    k_scale<<<(NN * FH / 8 + 255) / 256, 256>>>(d_h);

    // layer 1 aggregate + head projection into z rows
    k_agg1_proj<<<(NN + 15) / 16, 512>>>(d_h, b1, d_z);
    // layer 2 aggregate over z + log-softmax (also re-zeroes counts)
    k_agg2<<<(NN + 7) / 8, 256>>>(d_z, out);
}